// round 7
// baseline (speedup 1.0000x reference)
#include <cuda_runtime.h>
#include <cuda_bf16.h>
#include <math.h>
#include <stdint.h>

#define N_NODES 50000
#define NTOT    (2 * N_NODES)
#define NEDGE   800000
#define ETOT    (2 * NEDGE)
#define M_TILES ((N_NODES + 127) / 128)   // 391 per graph

// ================= device scratch =================
__device__ int   g_count[NTOT];
__device__ int   g_row_start[NTOT + 1];
__device__ int   g_cursor[NTOT];
__device__ int   g_srcsort[ETOT];
__device__ __nv_bfloat16 g_xhi[(size_t)NTOT * 128];
__device__ __nv_bfloat16 g_xlo[(size_t)NTOT * 128];
__device__ __nv_bfloat16 g_hhi[(size_t)NTOT * 256];
__device__ __nv_bfloat16 g_hlo[(size_t)NTOT * 256];
__device__ __nv_bfloat16 g_ahi[(size_t)NTOT * 128];
__device__ __nv_bfloat16 g_alo[(size_t)NTOT * 128];
__device__ float g_pq[(size_t)NTOT * 256];
__device__ __nv_bfloat16 g_whi[8 * 32768];
__device__ __nv_bfloat16 g_wlo[8 * 32768];

// ================= helpers =================
__device__ __forceinline__ uint32_t smem_u32(const void* p) {
    uint32_t a;
    asm("{ .reg .u64 t; cvta.to.shared.u64 t, %1; cvt.u32.u64 %0, t; }" : "=r"(a) : "l"(p));
    return a;
}
__device__ __forceinline__ void cp_async16(uint32_t dst, const void* src, bool valid) {
    if (valid) {
        asm volatile("cp.async.cg.shared.global [%0], [%1], 16;" :: "r"(dst), "l"(src));
    } else {
        asm volatile("cp.async.cg.shared.global [%0], [%1], 16, %2;"
                     :: "r"(dst), "l"(src), "r"(0u));
    }
}
#define CP_COMMIT()  asm volatile("cp.async.commit_group;" ::: "memory")
#define CP_WAIT1()   asm volatile("cp.async.wait_group 1;" ::: "memory")

__device__ __forceinline__ void ldsm4(uint32_t* r, uint32_t addr) {
    asm volatile("ldmatrix.sync.aligned.m8n8.x4.shared.b16 {%0,%1,%2,%3}, [%4];"
                 : "=r"(r[0]), "=r"(r[1]), "=r"(r[2]), "=r"(r[3]) : "r"(addr));
}
__device__ __forceinline__ void mma16816(float* d, const uint32_t* a, const uint32_t* b) {
    asm volatile(
        "mma.sync.aligned.m16n8k16.row.col.f32.bf16.bf16.f32 "
        "{%0,%1,%2,%3}, {%4,%5,%6,%7}, {%8,%9}, {%0,%1,%2,%3};"
        : "+f"(d[0]), "+f"(d[1]), "+f"(d[2]), "+f"(d[3])
        : "r"(a[0]), "r"(a[1]), "r"(a[2]), "r"(a[3]), "r"(b[0]), "r"(b[1]));
}

// fast tanh: 1 - 2/(e^{2x}+1).
__device__ __forceinline__ float fast_tanh(float x) {
    float e = __expf(2.0f * x);
    return 1.0f - __fdividef(2.0f, e + 1.0f);
}

// ================= upfront split of all fp32 inputs -> bf16 hi/lo =================
struct SplitJobs {
    const float* src[10];
    __nv_bfloat16* hi[10];
    __nv_bfloat16* lo[10];
    int n4cum[11];
};

__global__ void split_all_kernel(SplitJobs J) {
    int f = blockIdx.x * blockDim.x + threadIdx.x;
    if (f >= J.n4cum[10]) return;
    int j = 0;
#pragma unroll
    for (int t = 0; t < 10; t++)
        if (f >= J.n4cum[t + 1]) j = t + 1;
    int local = f - J.n4cum[j];
    float4 v = *(const float4*)(J.src[j] + 4 * (size_t)local);
    __nv_bfloat16 hx = __float2bfloat16(v.x);
    __nv_bfloat16 hy = __float2bfloat16(v.y);
    __nv_bfloat16 hz = __float2bfloat16(v.z);
    __nv_bfloat16 hw = __float2bfloat16(v.w);
    __nv_bfloat162 h01, h23, l01, l23;
    h01.x = hx; h01.y = hy; h23.x = hz; h23.y = hw;
    l01.x = __float2bfloat16(v.x - __bfloat162float(hx));
    l01.y = __float2bfloat16(v.y - __bfloat162float(hy));
    l23.x = __float2bfloat16(v.z - __bfloat162float(hz));
    l23.y = __float2bfloat16(v.w - __bfloat162float(hw));
    *(__nv_bfloat162*)(J.hi[j] + 4 * (size_t)local) = h01;
    *(__nv_bfloat162*)(J.hi[j] + 4 * (size_t)local + 2) = h23;
    *(__nv_bfloat162*)(J.lo[j] + 4 * (size_t)local) = l01;
    *(__nv_bfloat162*)(J.lo[j] + 4 * (size_t)local + 2) = l23;
}

// ================= merged CSR build over both graphs =================
__global__ void hist_kernel(const int* __restrict__ ei0, const int* __restrict__ ei1,
                            int* __restrict__ count) {
    int e = blockIdx.x * blockDim.x + threadIdx.x;
    if (e >= ETOT) return;
    int d;
    if (e < NEDGE) d = ei0[NEDGE + e];
    else           d = ei1[NEDGE + (e - NEDGE)] + N_NODES;
    atomicAdd(&count[d], 1);
}

__global__ void scan_kernel(const int* __restrict__ counts, int* __restrict__ row_start,
                            int* __restrict__ cursor, int n) {
    __shared__ int warp_sums[32];
    int tid = threadIdx.x;
    int lane = tid & 31;
    int w = tid >> 5;
    int carry = 0;
    for (int base = 0; base < n; base += 1024) {
        int i = base + tid;
        int v = (i < n) ? counts[i] : 0;
        int x = v;
#pragma unroll
        for (int off = 1; off < 32; off <<= 1) {
            int t = __shfl_up_sync(0xFFFFFFFFu, x, off);
            if (lane >= off) x += t;
        }
        if (lane == 31) warp_sums[w] = x;
        __syncthreads();
        if (w == 0) {
            int s = warp_sums[lane];
#pragma unroll
            for (int off = 1; off < 32; off <<= 1) {
                int t = __shfl_up_sync(0xFFFFFFFFu, s, off);
                if (lane >= off) s += t;
            }
            warp_sums[lane] = s;
        }
        __syncthreads();
        int wpre = (w > 0) ? warp_sums[w - 1] : 0;
        int incl = x + wpre;
        if (i < n) {
            int rs = carry + incl - v;
            row_start[i] = rs;
            cursor[i] = rs;
        }
        int total = warp_sums[31];
        __syncthreads();
        carry += total;
    }
    if (tid == 0) row_start[n] = carry;
}

__global__ void scatter_kernel(const int* __restrict__ ei0, const int* __restrict__ ei1,
                               int* __restrict__ cursor, int* __restrict__ srcsort) {
    int e = blockIdx.x * blockDim.x + threadIdx.x;
    if (e >= ETOT) return;
    int s, d;
    if (e < NEDGE) {
        s = ei0[e];
        d = ei0[NEDGE + e];
    } else {
        int e1 = e - NEDGE;
        s = ei1[e1] + N_NODES;
        d = ei1[NEDGE + e1] + N_NODES;
    }
    int p = atomicAdd(&cursor[d], 1);
    srcsort[p] = s;
}

// ================= layer-1 mean aggregation (bf16 pairs, unrolled) =================
__global__ void aggregate1_kernel(const __nv_bfloat16* __restrict__ xhi,
                                  const __nv_bfloat16* __restrict__ xlo,
                                  const int* __restrict__ row_start,
                                  const int* __restrict__ srcsort,
                                  __nv_bfloat16* __restrict__ ohi,
                                  __nv_bfloat16* __restrict__ olo) {
    int local = threadIdx.x >> 6;            // 2 nodes per 128-thread block
    int t2 = (threadIdx.x & 63) * 2;
    int node = blockIdx.x * 2 + local;
    int s0 = row_start[node];
    int s1 = row_start[node + 1];
    float ax = 0.f, ay = 0.f;
    int e = s0;
    for (; e + 2 <= s1; e += 2) {
        int sA = srcsort[e], sB = srcsort[e + 1];
        size_t bA = (size_t)sA * 128 + t2;
        size_t bB = (size_t)sB * 128 + t2;
        __nv_bfloat162 hA = *(const __nv_bfloat162*)(xhi + bA);
        __nv_bfloat162 lA = *(const __nv_bfloat162*)(xlo + bA);
        __nv_bfloat162 hB = *(const __nv_bfloat162*)(xhi + bB);
        __nv_bfloat162 lB = *(const __nv_bfloat162*)(xlo + bB);
        ax += __bfloat162float(hA.x) + __bfloat162float(lA.x) +
              __bfloat162float(hB.x) + __bfloat162float(lB.x);
        ay += __bfloat162float(hA.y) + __bfloat162float(lA.y) +
              __bfloat162float(hB.y) + __bfloat162float(lB.y);
    }
    if (e < s1) {
        int s = srcsort[e];
        size_t base = (size_t)s * 128 + t2;
        __nv_bfloat162 h = *(const __nv_bfloat162*)(xhi + base);
        __nv_bfloat162 l = *(const __nv_bfloat162*)(xlo + base);
        ax += __bfloat162float(h.x) + __bfloat162float(l.x);
        ay += __bfloat162float(h.y) + __bfloat162float(l.y);
    }
    float inv = 1.0f / (float)max(s1 - s0, 1);
    ax *= inv; ay *= inv;
    __nv_bfloat16 hx = __float2bfloat16(ax);
    __nv_bfloat16 hy = __float2bfloat16(ay);
    __nv_bfloat162 ph, pl;
    ph.x = hx; ph.y = hy;
    pl.x = __float2bfloat16(ax - __bfloat162float(hx));
    pl.y = __float2bfloat16(ay - __bfloat162float(hy));
    size_t ob = (size_t)node * 128 + t2;
    *(__nv_bfloat162*)(ohi + ob) = ph;
    *(__nv_bfloat162*)(olo + ob) = pl;
}

// ================= layer-2 fused aggregation + epilogue (unrolled) =================
__global__ void agg_fuse2_kernel(const float* __restrict__ pq,
                                 const int* __restrict__ row_start,
                                 const int* __restrict__ srcsort,
                                 const float* __restrict__ b2_0,
                                 const float* __restrict__ b2_1,
                                 float* __restrict__ out) {
    int local = threadIdx.x >> 5;            // 4 nodes per 128-thread block
    int t4 = (threadIdx.x & 31) * 4;
    int node = blockIdx.x * 4 + local;
    int s0 = row_start[node];
    int s1 = row_start[node + 1];
    float4 acc = make_float4(0.f, 0.f, 0.f, 0.f);
    int e = s0;
    for (; e + 2 <= s1; e += 2) {
        float4 vA = *(const float4*)(pq + (size_t)srcsort[e] * 256 + t4);
        float4 vB = *(const float4*)(pq + (size_t)srcsort[e + 1] * 256 + t4);
        acc.x += vA.x + vB.x; acc.y += vA.y + vB.y;
        acc.z += vA.z + vB.z; acc.w += vA.w + vB.w;
    }
    if (e < s1) {
        float4 v = *(const float4*)(pq + (size_t)srcsort[e] * 256 + t4);
        acc.x += v.x; acc.y += v.y; acc.z += v.z; acc.w += v.w;
    }
    float inv = 1.0f / (float)max(s1 - s0, 1);
    const float* b = (node < N_NODES) ? b2_0 : b2_1;
    float4 q = *(const float4*)(pq + (size_t)node * 256 + 128 + t4);
    float4 bb = *(const float4*)(b + t4);
    float4 o;
    o.x = fast_tanh(acc.x * inv + q.x + bb.x);
    o.y = fast_tanh(acc.y * inv + q.y + bb.y);
    o.z = fast_tanh(acc.z * inv + q.z + bb.z);
    o.w = fast_tanh(acc.w * inv + q.w + bb.w);
    *(float4*)(out + (size_t)node * 128 + t4) = o;
}

// ================= mma.sync split-bf16 GEMM (batched graphs) =================
struct GemmW {
    const __nv_bfloat16* b0hi[2][2];
    const __nv_bfloat16* b0lo[2][2];
    const __nv_bfloat16* b1hi[2][2];
    const __nv_bfloat16* b1lo[2][2];
    const float* bias[2];
};

template <int NT, int KHALF, int ASTRIDE, int BSTRIDE, int BOFF, bool SPLIT>
__global__ void __launch_bounds__(256, 2)
sage_mma_kernel(const __nv_bfloat16* __restrict__ a0hi, const __nv_bfloat16* __restrict__ a0lo,
                const __nv_bfloat16* __restrict__ a1hi, const __nv_bfloat16* __restrict__ a1lo,
                GemmW W,
                __nv_bfloat16* __restrict__ ohi, __nv_bfloat16* __restrict__ olo,
                float* __restrict__ ofp) {
    constexpr int NC = 2 * KHALF / 32;
    constexpr int MATB_A = 10240;
    constexpr int MATB_B = NT * 80;
    constexpr int STAGE = 2 * MATB_A + 2 * MATB_B;
    constexpr int WARPS_M = 2;
    constexpr int ROWS_W = 64;
    constexpr int MT = 4;
    constexpr int ITERS = (256 + 2 * NT) * 4 / 256;

    extern __shared__ char smem[];
    uint32_t sb = smem_u32(smem);

    int tid = threadIdx.x;
    int wid = tid >> 5;
    int lane = tid & 31;
    int wm = wid % WARPS_M;
    int wn = wid / WARPS_M;
    int y = blockIdx.y;
    int g = blockIdx.z;
    int m0 = g * N_NODES + blockIdx.x * 128;
    int Mlim = (g + 1) * N_NODES;
    int n0 = y * NT;
    int bn0 = y * BOFF;

    const __nv_bfloat16* B0h = W.b0hi[y][g];
    const __nv_bfloat16* B0l = W.b0lo[y][g];
    const __nv_bfloat16* B1h = W.b1hi[y][g];
    const __nv_bfloat16* B1l = W.b1lo[y][g];

    auto issue = [&](int c) {
        int half = (c * 32 >= KHALF) ? 1 : 0;
        int kh0 = c * 32 - half * KHALF;
        const __nv_bfloat16* Ah = half ? a1hi : a0hi;
        const __nv_bfloat16* Al = half ? a1lo : a0lo;
        const __nv_bfloat16* Bh = half ? B1h : B0h;
        const __nv_bfloat16* Bl = half ? B1l : B0l;
        uint32_t st = sb + (c & 1) * STAGE;
#pragma unroll
        for (int i = 0; i < ITERS; i++) {
            int idx = i * 256 + tid;
            int ch = idx & 3;
            if (idx < 1024) {
                int mat = idx >> 9;
                int r = (idx >> 2) & 127;
                int m = m0 + r;
                bool valid = (m < Mlim);
                const __nv_bfloat16* src = (mat ? Al : Ah);
                const __nv_bfloat16* p = src + (size_t)(valid ? m : 0) * ASTRIDE + kh0 + ch * 8;
                cp_async16(st + mat * MATB_A + r * 80 + ch * 16, p, valid);
            } else {
                int idx2 = idx - 1024;
                int matb = idx2 / (NT * 4);
                int r = (idx2 >> 2) % NT;
                const __nv_bfloat16* src = (matb ? Bl : Bh);
                cp_async16(st + 2 * MATB_A + matb * MATB_B + r * 80 + ch * 16,
                           src + (size_t)(bn0 + r) * BSTRIDE + kh0 + ch * 8, true);
            }
        }
    };

    float acc[MT][4][4];
#pragma unroll
    for (int i = 0; i < MT; i++)
#pragma unroll
        for (int j = 0; j < 4; j++)
#pragma unroll
            for (int k = 0; k < 4; k++) acc[i][j][k] = 0.f;

    issue(0); CP_COMMIT();
    issue(1); CP_COMMIT();

    uint32_t a_row = (uint32_t)(wm * ROWS_W + (lane & 15)) * 80 + (lane >> 4) * 16;
    uint32_t b_row = (uint32_t)(wn * 32 + (lane & 7) + ((lane >> 4) << 3)) * 80 +
                     ((lane >> 3) & 1) * 16;

    for (int c = 0; c < NC; c++) {
        CP_WAIT1();
        __syncthreads();
        uint32_t st = sb + (c & 1) * STAGE;
#pragma unroll
        for (int ks = 0; ks < 2; ks++) {
            uint32_t ko = ks * 32;
            uint32_t Ahf[MT][4], Alf[MT][4], Bhf[2][4], Blf[2][4];
#pragma unroll
            for (int mt = 0; mt < MT; mt++) {
                uint32_t ar = st + a_row + (uint32_t)mt * (16 * 80) + ko;
                ldsm4(Ahf[mt], ar);
                ldsm4(Alf[mt], ar + MATB_A);
            }
#pragma unroll
            for (int nt2 = 0; nt2 < 2; nt2++) {
                uint32_t br = st + 2 * MATB_A + b_row + (uint32_t)nt2 * (16 * 80) + ko;
                ldsm4(Bhf[nt2], br);
                ldsm4(Blf[nt2], br + MATB_B);
            }
#pragma unroll
            for (int mt = 0; mt < MT; mt++) {
#pragma unroll
                for (int nt = 0; nt < 4; nt++) {
                    const uint32_t* bh = &Bhf[nt >> 1][(nt & 1) * 2];
                    const uint32_t* bl = &Blf[nt >> 1][(nt & 1) * 2];
                    mma16816(acc[mt][nt], Ahf[mt], bh);
                    mma16816(acc[mt][nt], Ahf[mt], bl);
                    mma16816(acc[mt][nt], Alf[mt], bh);
                }
            }
        }
        __syncthreads();
        if (c + 2 < NC) issue(c + 2);
        CP_COMMIT();
    }

    int gq = lane >> 2, t4 = lane & 3;
    const float* bias = SPLIT ? W.bias[g] : nullptr;
#pragma unroll
    for (int mt = 0; mt < MT; mt++) {
#pragma unroll
        for (int nt = 0; nt < 4; nt++) {
            int col = n0 + wn * 32 + nt * 8 + 2 * t4;
            float b0 = SPLIT ? bias[col] : 0.f;
            float b1 = SPLIT ? bias[col + 1] : 0.f;
#pragma unroll
            for (int hrow = 0; hrow < 2; hrow++) {
                int row = m0 + wm * ROWS_W + mt * 16 + gq + hrow * 8;
                if (row < Mlim) {
                    size_t ob = (size_t)row * 256 + col;
                    if (SPLIT) {
                        float v0 = fast_tanh(acc[mt][nt][2 * hrow + 0] + b0);
                        float v1 = fast_tanh(acc[mt][nt][2 * hrow + 1] + b1);
                        __nv_bfloat16 h0 = __float2bfloat16(v0);
                        __nv_bfloat16 h1 = __float2bfloat16(v1);
                        __nv_bfloat162 ph; ph.x = h0; ph.y = h1;
                        __nv_bfloat162 pl;
                        pl.x = __float2bfloat16(v0 - __bfloat162float(h0));
                        pl.y = __float2bfloat16(v1 - __bfloat162float(h1));
                        *(__nv_bfloat162*)(ohi + ob) = ph;
                        *(__nv_bfloat162*)(olo + ob) = pl;
                    } else {
                        float2 o;
                        o.x = acc[mt][nt][2 * hrow + 0];
                        o.y = acc[mt][nt][2 * hrow + 1];
                        *(float2*)(ofp + ob) = o;
                    }
                }
            }
        }
    }
}

// ================= host =================
extern "C" void kernel_launch(void* const* d_in, const int* in_sizes, int n_in,
                              void* d_out, int out_size) {
    (void)in_sizes; (void)n_in; (void)out_size;

    const float* x0  = (const float*)d_in[0];
    const float* x1  = (const float*)d_in[1];
    const int*   ei0 = (const int*)d_in[2];
    const int*   ei1 = (const int*)d_in[3];
    const float* W1l_0 = (const float*)d_in[4];
    const float* b1_0  = (const float*)d_in[5];
    const float* W1r_0 = (const float*)d_in[6];
    const float* W2l_0 = (const float*)d_in[7];
    const float* b2_0  = (const float*)d_in[8];
    const float* W2r_0 = (const float*)d_in[9];
    const float* W1l_1 = (const float*)d_in[10];
    const float* b1_1  = (const float*)d_in[11];
    const float* W1r_1 = (const float*)d_in[12];
    const float* W2l_1 = (const float*)d_in[13];
    const float* b2_1  = (const float*)d_in[14];
    const float* W2r_1 = (const float*)d_in[15];
    float* out = (float*)d_out;

    constexpr int SMEM = 2 * (2 * 10240 + 2 * 128 * 80);  // 81920
    cudaFuncSetAttribute((const void*)sage_mma_kernel<128, 128, 128, 128, 128, true>,
                         cudaFuncAttributeMaxDynamicSharedMemorySize, SMEM);
    cudaFuncSetAttribute((const void*)sage_mma_kernel<128, 128, 256, 256, 0, false>,
                         cudaFuncAttributeMaxDynamicSharedMemorySize, SMEM);

    int *count, *row_start, *cursor, *srcsort;
    __nv_bfloat16 *xhi, *xlo, *hhi, *hlo, *ahi, *alo, *whi, *wlo;
    float* pq;
    cudaGetSymbolAddress((void**)&count, g_count);
    cudaGetSymbolAddress((void**)&row_start, g_row_start);
    cudaGetSymbolAddress((void**)&cursor, g_cursor);
    cudaGetSymbolAddress((void**)&srcsort, g_srcsort);
    cudaGetSymbolAddress((void**)&xhi, g_xhi);
    cudaGetSymbolAddress((void**)&xlo, g_xlo);
    cudaGetSymbolAddress((void**)&hhi, g_hhi);
    cudaGetSymbolAddress((void**)&hlo, g_hlo);
    cudaGetSymbolAddress((void**)&ahi, g_ahi);
    cudaGetSymbolAddress((void**)&alo, g_alo);
    cudaGetSymbolAddress((void**)&pq, g_pq);
    cudaGetSymbolAddress((void**)&whi, g_whi);
    cudaGetSymbolAddress((void**)&wlo, g_wlo);

    SplitJobs J;
    const float* srcs[10] = {x0, x1, W1l_0, W1r_0, W2l_0, W2r_0, W1l_1, W1r_1, W2l_1, W2r_1};
    int counts[10] = {N_NODES * 128, N_NODES * 128,
                      32768, 32768, 32768, 32768, 32768, 32768, 32768, 32768};
    int cum = 0;
    for (int j = 0; j < 10; j++) {
        J.src[j] = srcs[j];
        if (j == 0)      { J.hi[j] = xhi;                          J.lo[j] = xlo; }
        else if (j == 1) { J.hi[j] = xhi + (size_t)N_NODES * 128;
                           J.lo[j] = xlo + (size_t)N_NODES * 128; }
        else             { J.hi[j] = whi + (j - 2) * 32768;
                           J.lo[j] = wlo + (j - 2) * 32768; }
        J.n4cum[j] = cum;
        cum += counts[j] / 4;
    }
    J.n4cum[10] = cum;

    // ---- fork: split on side stream, CSR chain on main stream ----
    cudaStream_t s2;
    cudaStreamCreateWithFlags(&s2, cudaStreamNonBlocking);
    cudaEvent_t evFork, evJoin;
    cudaEventCreateWithFlags(&evFork, cudaEventDisableTiming);
    cudaEventCreateWithFlags(&evJoin, cudaEventDisableTiming);

    cudaEventRecord(evFork, 0);
    cudaStreamWaitEvent(s2, evFork, 0);
    split_all_kernel<<<(cum + 255) / 256, 256, 0, s2>>>(J);
    cudaEventRecord(evJoin, s2);

    cudaMemsetAsync(count, 0, NTOT * sizeof(int));
    hist_kernel<<<(ETOT + 255) / 256, 256>>>(ei0, ei1, count);
    scan_kernel<<<1, 1024>>>(count, row_start, cursor, NTOT);
    scatter_kernel<<<(ETOT + 255) / 256, 256>>>(ei0, ei1, cursor, srcsort);

    cudaStreamWaitEvent(0, evJoin, 0);   // join: split must finish before agg1/gemm1

    GemmW W1, W2;
    for (int g = 0; g < 2; g++) {
        for (int y = 0; y < 2; y++) {
            W1.b0hi[y][g] = whi + (4 * g + 0) * 32768; W1.b0lo[y][g] = wlo + (4 * g + 0) * 32768;
            W1.b1hi[y][g] = whi + (4 * g + 1) * 32768; W1.b1lo[y][g] = wlo + (4 * g + 1) * 32768;
        }
        W2.b0hi[0][g] = whi + (4 * g + 2) * 32768;       W2.b0lo[0][g] = wlo + (4 * g + 2) * 32768;
        W2.b1hi[0][g] = whi + (4 * g + 2) * 32768 + 128; W2.b1lo[0][g] = wlo + (4 * g + 2) * 32768 + 128;
        W2.b0hi[1][g] = whi + (4 * g + 3) * 32768;       W2.b0lo[1][g] = wlo + (4 * g + 3) * 32768;
        W2.b1hi[1][g] = whi + (4 * g + 3) * 32768 + 128; W2.b1lo[1][g] = wlo + (4 * g + 3) * 32768 + 128;
    }
    W1.bias[0] = b1_0; W1.bias[1] = b1_1;
    W2.bias[0] = b2_0; W2.bias[1] = b2_1;

    aggregate1_kernel<<<NTOT / 2, 128>>>(xhi, xlo, row_start, srcsort, ahi, alo);
    {
        dim3 grid(M_TILES, 2, 2);
        sage_mma_kernel<128, 128, 128, 128, 128, true><<<grid, 256, SMEM>>>(
            ahi, alo, xhi, xlo, W1, hhi, hlo, nullptr);
    }
    {
        dim3 grid(M_TILES, 2, 2);
        sage_mma_kernel<128, 128, 256, 256, 0, false><<<grid, 256, SMEM>>>(
            hhi, hlo, hhi + 128, hlo + 128, W2, nullptr, nullptr, pq);
    }
    agg_fuse2_kernel<<<NTOT / 4, 128>>>(pq, row_start, srcsort, b2_0, b2_1, out);

    cudaEventDestroy(evFork);
    cudaEventDestroy(evJoin);
    cudaStreamDestroy(s2);
}

// round 8
// speedup vs baseline: 1.1093x; 1.1093x over previous
#include <cuda_runtime.h>
#include <cuda_bf16.h>
#include <cuda_fp16.h>
#include <math.h>
#include <stdint.h>

#define N_NODES 50000
#define NTOT    (2 * N_NODES)
#define NEDGE   800000
#define ETOT    (2 * NEDGE)
#define M_TILES ((N_NODES + 127) / 128)   // 391 per graph

// ================= device scratch =================
__device__ int   g_count[NTOT];
__device__ int   g_row_start[NTOT + 1];
__device__ int   g_cursor[NTOT];
__device__ int   g_srcsort[ETOT];
__device__ __nv_bfloat16 g_xhi[(size_t)NTOT * 128];
__device__ __nv_bfloat16 g_xlo[(size_t)NTOT * 128];
__device__ __half        g_xh16[(size_t)NTOT * 128];
__device__ __nv_bfloat16 g_hhi[(size_t)NTOT * 256];
__device__ __nv_bfloat16 g_hlo[(size_t)NTOT * 256];
__device__ __nv_bfloat16 g_ahi[(size_t)NTOT * 128];
__device__ __nv_bfloat16 g_alo[(size_t)NTOT * 128];
__device__ __half g_p[(size_t)NTOT * 128];
__device__ float  g_q[(size_t)NTOT * 128];
__device__ __nv_bfloat16 g_whi[8 * 32768];
__device__ __nv_bfloat16 g_wlo[8 * 32768];

// ================= helpers =================
__device__ __forceinline__ uint32_t smem_u32(const void* p) {
    uint32_t a;
    asm("{ .reg .u64 t; cvta.to.shared.u64 t, %1; cvt.u32.u64 %0, t; }" : "=r"(a) : "l"(p));
    return a;
}
__device__ __forceinline__ void cp_async16(uint32_t dst, const void* src, bool valid) {
    if (valid) {
        asm volatile("cp.async.cg.shared.global [%0], [%1], 16;" :: "r"(dst), "l"(src));
    } else {
        asm volatile("cp.async.cg.shared.global [%0], [%1], 16, %2;"
                     :: "r"(dst), "l"(src), "r"(0u));
    }
}
#define CP_COMMIT()  asm volatile("cp.async.commit_group;" ::: "memory")
#define CP_WAIT1()   asm volatile("cp.async.wait_group 1;" ::: "memory")

__device__ __forceinline__ void ldsm4(uint32_t* r, uint32_t addr) {
    asm volatile("ldmatrix.sync.aligned.m8n8.x4.shared.b16 {%0,%1,%2,%3}, [%4];"
                 : "=r"(r[0]), "=r"(r[1]), "=r"(r[2]), "=r"(r[3]) : "r"(addr));
}
__device__ __forceinline__ void mma16816(float* d, const uint32_t* a, const uint32_t* b) {
    asm volatile(
        "mma.sync.aligned.m16n8k16.row.col.f32.bf16.bf16.f32 "
        "{%0,%1,%2,%3}, {%4,%5,%6,%7}, {%8,%9}, {%0,%1,%2,%3};"
        : "+f"(d[0]), "+f"(d[1]), "+f"(d[2]), "+f"(d[3])
        : "r"(a[0]), "r"(a[1]), "r"(a[2]), "r"(a[3]), "r"(b[0]), "r"(b[1]));
}

__device__ __forceinline__ float fast_tanh(float x) {
    float e = __expf(2.0f * x);
    return 1.0f - __fdividef(2.0f, e + 1.0f);
}

// ================= upfront split of all fp32 inputs =================
struct SplitJobs {
    const float* src[10];
    __nv_bfloat16* hi[10];
    __nv_bfloat16* lo[10];
    __half* f16[10];          // optional fp16 copy (x jobs only)
    int n4cum[11];
};

__global__ void split_all_kernel(SplitJobs J) {
    int f = blockIdx.x * blockDim.x + threadIdx.x;
    if (f >= J.n4cum[10]) return;
    int j = 0;
#pragma unroll
    for (int t = 0; t < 10; t++)
        if (f >= J.n4cum[t + 1]) j = t + 1;
    int local = f - J.n4cum[j];
    float4 v = *(const float4*)(J.src[j] + 4 * (size_t)local);
    __nv_bfloat16 hx = __float2bfloat16(v.x);
    __nv_bfloat16 hy = __float2bfloat16(v.y);
    __nv_bfloat16 hz = __float2bfloat16(v.z);
    __nv_bfloat16 hw = __float2bfloat16(v.w);
    __nv_bfloat162 h01, h23, l01, l23;
    h01.x = hx; h01.y = hy; h23.x = hz; h23.y = hw;
    l01.x = __float2bfloat16(v.x - __bfloat162float(hx));
    l01.y = __float2bfloat16(v.y - __bfloat162float(hy));
    l23.x = __float2bfloat16(v.z - __bfloat162float(hz));
    l23.y = __float2bfloat16(v.w - __bfloat162float(hw));
    *(__nv_bfloat162*)(J.hi[j] + 4 * (size_t)local) = h01;
    *(__nv_bfloat162*)(J.hi[j] + 4 * (size_t)local + 2) = h23;
    *(__nv_bfloat162*)(J.lo[j] + 4 * (size_t)local) = l01;
    *(__nv_bfloat162*)(J.lo[j] + 4 * (size_t)local + 2) = l23;
    if (J.f16[j]) {
        __half2 a = __floats2half2_rn(v.x, v.y);
        __half2 b = __floats2half2_rn(v.z, v.w);
        uint2 pk;
        pk.x = *(uint32_t*)&a;
        pk.y = *(uint32_t*)&b;
        *(uint2*)(J.f16[j] + 4 * (size_t)local) = pk;
    }
}

// ================= merged CSR build =================
__global__ void hist_kernel(const int* __restrict__ ei0, const int* __restrict__ ei1,
                            int* __restrict__ count) {
    int e = blockIdx.x * blockDim.x + threadIdx.x;
    if (e >= ETOT) return;
    int d;
    if (e < NEDGE) d = ei0[NEDGE + e];
    else           d = ei1[NEDGE + (e - NEDGE)] + N_NODES;
    atomicAdd(&count[d], 1);
}

// scan also resets count to 0 for the next graph replay (globals start zeroed).
__global__ void scan_kernel(int* __restrict__ counts, int* __restrict__ row_start,
                            int* __restrict__ cursor, int n) {
    __shared__ int warp_sums[32];
    int tid = threadIdx.x;
    int lane = tid & 31;
    int w = tid >> 5;
    int carry = 0;
    for (int base = 0; base < n; base += 1024) {
        int i = base + tid;
        int v = 0;
        if (i < n) { v = counts[i]; counts[i] = 0; }
        int x = v;
#pragma unroll
        for (int off = 1; off < 32; off <<= 1) {
            int t = __shfl_up_sync(0xFFFFFFFFu, x, off);
            if (lane >= off) x += t;
        }
        if (lane == 31) warp_sums[w] = x;
        __syncthreads();
        if (w == 0) {
            int s = warp_sums[lane];
#pragma unroll
            for (int off = 1; off < 32; off <<= 1) {
                int t = __shfl_up_sync(0xFFFFFFFFu, s, off);
                if (lane >= off) s += t;
            }
            warp_sums[lane] = s;
        }
        __syncthreads();
        int wpre = (w > 0) ? warp_sums[w - 1] : 0;
        int incl = x + wpre;
        if (i < n) {
            int rs = carry + incl - v;
            row_start[i] = rs;
            cursor[i] = rs;
        }
        int total = warp_sums[31];
        __syncthreads();
        carry += total;
    }
    if (tid == 0) row_start[n] = carry;
}

__global__ void scatter_kernel(const int* __restrict__ ei0, const int* __restrict__ ei1,
                               int* __restrict__ cursor, int* __restrict__ srcsort) {
    int e = blockIdx.x * blockDim.x + threadIdx.x;
    if (e >= ETOT) return;
    int s, d;
    if (e < NEDGE) {
        s = ei0[e];
        d = ei0[NEDGE + e];
    } else {
        int e1 = e - NEDGE;
        s = ei1[e1] + N_NODES;
        d = ei1[NEDGE + e1] + N_NODES;
    }
    int p = atomicAdd(&cursor[d], 1);
    srcsort[p] = s;
}

// ================= layer-1 mean aggregation: fp16 x gathers =================
// 4 nodes per 128-thread block; 32 threads/node; 4 dims/thread (8B per edge).
__global__ void aggregate1_kernel(const __half* __restrict__ xh,
                                  const int* __restrict__ row_start,
                                  const int* __restrict__ srcsort,
                                  __nv_bfloat16* __restrict__ ohi,
                                  __nv_bfloat16* __restrict__ olo) {
    int local = threadIdx.x >> 5;
    int t4 = (threadIdx.x & 31) * 4;
    int node = blockIdx.x * 4 + local;
    int s0 = row_start[node];
    int s1 = row_start[node + 1];
    float a0 = 0.f, a1 = 0.f, a2 = 0.f, a3 = 0.f;
    int e = s0;
    for (; e + 2 <= s1; e += 2) {
        uint2 vA = *(const uint2*)(xh + (size_t)srcsort[e] * 128 + t4);
        uint2 vB = *(const uint2*)(xh + (size_t)srcsort[e + 1] * 128 + t4);
        float2 fA0 = __half22float2(*(__half2*)&vA.x);
        float2 fA1 = __half22float2(*(__half2*)&vA.y);
        float2 fB0 = __half22float2(*(__half2*)&vB.x);
        float2 fB1 = __half22float2(*(__half2*)&vB.y);
        a0 += fA0.x + fB0.x; a1 += fA0.y + fB0.y;
        a2 += fA1.x + fB1.x; a3 += fA1.y + fB1.y;
    }
    if (e < s1) {
        uint2 v = *(const uint2*)(xh + (size_t)srcsort[e] * 128 + t4);
        float2 f0 = __half22float2(*(__half2*)&v.x);
        float2 f1 = __half22float2(*(__half2*)&v.y);
        a0 += f0.x; a1 += f0.y; a2 += f1.x; a3 += f1.y;
    }
    float inv = 1.0f / (float)max(s1 - s0, 1);
    a0 *= inv; a1 *= inv; a2 *= inv; a3 *= inv;
    __nv_bfloat16 h0 = __float2bfloat16(a0);
    __nv_bfloat16 h1 = __float2bfloat16(a1);
    __nv_bfloat16 h2 = __float2bfloat16(a2);
    __nv_bfloat16 h3 = __float2bfloat16(a3);
    __nv_bfloat162 ph01, ph23, pl01, pl23;
    ph01.x = h0; ph01.y = h1; ph23.x = h2; ph23.y = h3;
    pl01.x = __float2bfloat16(a0 - __bfloat162float(h0));
    pl01.y = __float2bfloat16(a1 - __bfloat162float(h1));
    pl23.x = __float2bfloat16(a2 - __bfloat162float(h2));
    pl23.y = __float2bfloat16(a3 - __bfloat162float(h3));
    size_t ob = (size_t)node * 128 + t4;
    *(__nv_bfloat162*)(ohi + ob) = ph01;
    *(__nv_bfloat162*)(ohi + ob + 2) = ph23;
    *(__nv_bfloat162*)(olo + ob) = pl01;
    *(__nv_bfloat162*)(olo + ob + 2) = pl23;
}

// ================= layer-2 fused aggregation + epilogue: fp16 p gathers ==========
__global__ void agg_fuse2_kernel(const __half* __restrict__ p,
                                 const float* __restrict__ q,
                                 const int* __restrict__ row_start,
                                 const int* __restrict__ srcsort,
                                 const float* __restrict__ b2_0,
                                 const float* __restrict__ b2_1,
                                 float* __restrict__ out) {
    int local = threadIdx.x >> 5;
    int t4 = (threadIdx.x & 31) * 4;
    int node = blockIdx.x * 4 + local;
    int s0 = row_start[node];
    int s1 = row_start[node + 1];
    float a0 = 0.f, a1 = 0.f, a2 = 0.f, a3 = 0.f;
    int e = s0;
    for (; e + 2 <= s1; e += 2) {
        uint2 vA = *(const uint2*)(p + (size_t)srcsort[e] * 128 + t4);
        uint2 vB = *(const uint2*)(p + (size_t)srcsort[e + 1] * 128 + t4);
        float2 fA0 = __half22float2(*(__half2*)&vA.x);
        float2 fA1 = __half22float2(*(__half2*)&vA.y);
        float2 fB0 = __half22float2(*(__half2*)&vB.x);
        float2 fB1 = __half22float2(*(__half2*)&vB.y);
        a0 += fA0.x + fB0.x; a1 += fA0.y + fB0.y;
        a2 += fA1.x + fB1.x; a3 += fA1.y + fB1.y;
    }
    if (e < s1) {
        uint2 v = *(const uint2*)(p + (size_t)srcsort[e] * 128 + t4);
        float2 f0 = __half22float2(*(__half2*)&v.x);
        float2 f1 = __half22float2(*(__half2*)&v.y);
        a0 += f0.x; a1 += f0.y; a2 += f1.x; a3 += f1.y;
    }
    float inv = 1.0f / (float)max(s1 - s0, 1);
    const float* b = (node < N_NODES) ? b2_0 : b2_1;
    float4 qq = *(const float4*)(q + (size_t)node * 128 + t4);
    float4 bb = *(const float4*)(b + t4);
    float4 o;
    o.x = fast_tanh(a0 * inv + qq.x + bb.x);
    o.y = fast_tanh(a1 * inv + qq.y + bb.y);
    o.z = fast_tanh(a2 * inv + qq.z + bb.z);
    o.w = fast_tanh(a3 * inv + qq.w + bb.w);
    *(float4*)(out + (size_t)node * 128 + t4) = o;
}

// ================= mma.sync split-bf16 GEMM (batched graphs) =================
struct GemmW {
    const __nv_bfloat16* b0hi[2][2];
    const __nv_bfloat16* b0lo[2][2];
    const __nv_bfloat16* b1hi[2][2];
    const __nv_bfloat16* b1lo[2][2];
    const float* bias[2];
};

// MODE 0: layer1 — out = tanh(acc+bias) -> bf16 hi/lo at row*256 + (y*128+col)
// MODE 1: layer2 — y==0: p(half) = acc; y==1: q(float) = acc; at row*128+col
template <int NT, int KHALF, int ASTRIDE, int BSTRIDE, int BOFF, int MODE>
__global__ void __launch_bounds__(256, 2)
sage_mma_kernel(const __nv_bfloat16* __restrict__ a0hi, const __nv_bfloat16* __restrict__ a0lo,
                const __nv_bfloat16* __restrict__ a1hi, const __nv_bfloat16* __restrict__ a1lo,
                GemmW W,
                __nv_bfloat16* __restrict__ ohi, __nv_bfloat16* __restrict__ olo,
                __half* __restrict__ op, float* __restrict__ oq) {
    constexpr int NC = 2 * KHALF / 32;
    constexpr int MATB_A = 10240;
    constexpr int MATB_B = NT * 80;
    constexpr int STAGE = 2 * MATB_A + 2 * MATB_B;
    constexpr int WARPS_M = 2;
    constexpr int ROWS_W = 64;
    constexpr int MT = 4;
    constexpr int ITERS = (256 + 2 * NT) * 4 / 256;

    extern __shared__ char smem[];
    uint32_t sb = smem_u32(smem);

    int tid = threadIdx.x;
    int wid = tid >> 5;
    int lane = tid & 31;
    int wm = wid % WARPS_M;
    int wn = wid / WARPS_M;
    int y = blockIdx.y;
    int g = blockIdx.z;
    int m0 = g * N_NODES + blockIdx.x * 128;
    int Mlim = (g + 1) * N_NODES;
    int n0 = y * NT;
    int bn0 = y * BOFF;

    const __nv_bfloat16* B0h = W.b0hi[y][g];
    const __nv_bfloat16* B0l = W.b0lo[y][g];
    const __nv_bfloat16* B1h = W.b1hi[y][g];
    const __nv_bfloat16* B1l = W.b1lo[y][g];

    auto issue = [&](int c) {
        int half = (c * 32 >= KHALF) ? 1 : 0;
        int kh0 = c * 32 - half * KHALF;
        const __nv_bfloat16* Ah = half ? a1hi : a0hi;
        const __nv_bfloat16* Al = half ? a1lo : a0lo;
        const __nv_bfloat16* Bh = half ? B1h : B0h;
        const __nv_bfloat16* Bl = half ? B1l : B0l;
        uint32_t st = sb + (c & 1) * STAGE;
#pragma unroll
        for (int i = 0; i < ITERS; i++) {
            int idx = i * 256 + tid;
            int ch = idx & 3;
            if (idx < 1024) {
                int mat = idx >> 9;
                int r = (idx >> 2) & 127;
                int m = m0 + r;
                bool valid = (m < Mlim);
                const __nv_bfloat16* src = (mat ? Al : Ah);
                const __nv_bfloat16* pp = src + (size_t)(valid ? m : 0) * ASTRIDE + kh0 + ch * 8;
                cp_async16(st + mat * MATB_A + r * 80 + ch * 16, pp, valid);
            } else {
                int idx2 = idx - 1024;
                int matb = idx2 / (NT * 4);
                int r = (idx2 >> 2) % NT;
                const __nv_bfloat16* src = (matb ? Bl : Bh);
                cp_async16(st + 2 * MATB_A + matb * MATB_B + r * 80 + ch * 16,
                           src + (size_t)(bn0 + r) * BSTRIDE + kh0 + ch * 8, true);
            }
        }
    };

    float acc[MT][4][4];
#pragma unroll
    for (int i = 0; i < MT; i++)
#pragma unroll
        for (int j = 0; j < 4; j++)
#pragma unroll
            for (int k = 0; k < 4; k++) acc[i][j][k] = 0.f;

    issue(0); CP_COMMIT();
    issue(1); CP_COMMIT();

    uint32_t a_row = (uint32_t)(wm * ROWS_W + (lane & 15)) * 80 + (lane >> 4) * 16;
    uint32_t b_row = (uint32_t)(wn * 32 + (lane & 7) + ((lane >> 4) << 3)) * 80 +
                     ((lane >> 3) & 1) * 16;

    for (int c = 0; c < NC; c++) {
        CP_WAIT1();
        __syncthreads();
        uint32_t st = sb + (c & 1) * STAGE;
#pragma unroll
        for (int ks = 0; ks < 2; ks++) {
            uint32_t ko = ks * 32;
            uint32_t Ahf[MT][4], Alf[MT][4], Bhf[2][4], Blf[2][4];
#pragma unroll
            for (int mt = 0; mt < MT; mt++) {
                uint32_t ar = st + a_row + (uint32_t)mt * (16 * 80) + ko;
                ldsm4(Ahf[mt], ar);
                ldsm4(Alf[mt], ar + MATB_A);
            }
#pragma unroll
            for (int nt2 = 0; nt2 < 2; nt2++) {
                uint32_t br = st + 2 * MATB_A + b_row + (uint32_t)nt2 * (16 * 80) + ko;
                ldsm4(Bhf[nt2], br);
                ldsm4(Blf[nt2], br + MATB_B);
            }
#pragma unroll
            for (int mt = 0; mt < MT; mt++) {
#pragma unroll
                for (int nt = 0; nt < 4; nt++) {
                    const uint32_t* bh = &Bhf[nt >> 1][(nt & 1) * 2];
                    const uint32_t* bl = &Blf[nt >> 1][(nt & 1) * 2];
                    mma16816(acc[mt][nt], Ahf[mt], bh);
                    mma16816(acc[mt][nt], Ahf[mt], bl);
                    mma16816(acc[mt][nt], Alf[mt], bh);
                }
            }
        }
        __syncthreads();
        if (c + 2 < NC) issue(c + 2);
        CP_COMMIT();
    }

    int gq = lane >> 2, t4 = lane & 3;
    const float* bias = (MODE == 0) ? W.bias[g] : nullptr;
#pragma unroll
    for (int mt = 0; mt < MT; mt++) {
#pragma unroll
        for (int nt = 0; nt < 4; nt++) {
            int col = wn * 32 + nt * 8 + 2 * t4;       // [0,128)
            float b0 = (MODE == 0) ? bias[n0 + col] : 0.f;
            float b1 = (MODE == 0) ? bias[n0 + col + 1] : 0.f;
#pragma unroll
            for (int hrow = 0; hrow < 2; hrow++) {
                int row = m0 + wm * ROWS_W + mt * 16 + gq + hrow * 8;
                if (row < Mlim) {
                    float v0 = acc[mt][nt][2 * hrow + 0];
                    float v1 = acc[mt][nt][2 * hrow + 1];
                    if (MODE == 0) {
                        v0 = fast_tanh(v0 + b0);
                        v1 = fast_tanh(v1 + b1);
                        __nv_bfloat16 h0 = __float2bfloat16(v0);
                        __nv_bfloat16 h1 = __float2bfloat16(v1);
                        __nv_bfloat162 ph; ph.x = h0; ph.y = h1;
                        __nv_bfloat162 pl;
                        pl.x = __float2bfloat16(v0 - __bfloat162float(h0));
                        pl.y = __float2bfloat16(v1 - __bfloat162float(h1));
                        size_t ob = (size_t)row * 256 + n0 + col;
                        *(__nv_bfloat162*)(ohi + ob) = ph;
                        *(__nv_bfloat162*)(olo + ob) = pl;
                    } else {
                        size_t ob = (size_t)row * 128 + col;
                        if (y == 0) {
                            __half2 h = __floats2half2_rn(v0, v1);
                            *(__half2*)(op + ob) = h;
                        } else {
                            float2 o; o.x = v0; o.y = v1;
                            *(float2*)(oq + ob) = o;
                        }
                    }
                }
            }
        }
    }
}

// ================= host =================
extern "C" void kernel_launch(void* const* d_in, const int* in_sizes, int n_in,
                              void* d_out, int out_size) {
    (void)in_sizes; (void)n_in; (void)out_size;

    const float* x0  = (const float*)d_in[0];
    const float* x1  = (const float*)d_in[1];
    const int*   ei0 = (const int*)d_in[2];
    const int*   ei1 = (const int*)d_in[3];
    const float* W1l_0 = (const float*)d_in[4];
    const float* b1_0  = (const float*)d_in[5];
    const float* W1r_0 = (const float*)d_in[6];
    const float* W2l_0 = (const float*)d_in[7];
    const float* b2_0  = (const float*)d_in[8];
    const float* W2r_0 = (const float*)d_in[9];
    const float* W1l_1 = (const float*)d_in[10];
    const float* b1_1  = (const float*)d_in[11];
    const float* W1r_1 = (const float*)d_in[12];
    const float* W2l_1 = (const float*)d_in[13];
    const float* b2_1  = (const float*)d_in[14];
    const float* W2r_1 = (const float*)d_in[15];
    float* out = (float*)d_out;

    constexpr int SMEM = 2 * (2 * 10240 + 2 * 128 * 80);  // 81920
    cudaFuncSetAttribute((const void*)sage_mma_kernel<128, 128, 128, 128, 128, 0>,
                         cudaFuncAttributeMaxDynamicSharedMemorySize, SMEM);
    cudaFuncSetAttribute((const void*)sage_mma_kernel<128, 128, 256, 256, 0, 1>,
                         cudaFuncAttributeMaxDynamicSharedMemorySize, SMEM);

    int *count, *row_start, *cursor, *srcsort;
    __nv_bfloat16 *xhi, *xlo, *hhi, *hlo, *ahi, *alo, *whi, *wlo;
    __half *xh16, *p;
    float *q;
    cudaGetSymbolAddress((void**)&count, g_count);
    cudaGetSymbolAddress((void**)&row_start, g_row_start);
    cudaGetSymbolAddress((void**)&cursor, g_cursor);
    cudaGetSymbolAddress((void**)&srcsort, g_srcsort);
    cudaGetSymbolAddress((void**)&xhi, g_xhi);
    cudaGetSymbolAddress((void**)&xlo, g_xlo);
    cudaGetSymbolAddress((void**)&xh16, g_xh16);
    cudaGetSymbolAddress((void**)&hhi, g_hhi);
    cudaGetSymbolAddress((void**)&hlo, g_hlo);
    cudaGetSymbolAddress((void**)&ahi, g_ahi);
    cudaGetSymbolAddress((void**)&alo, g_alo);
    cudaGetSymbolAddress((void**)&p, g_p);
    cudaGetSymbolAddress((void**)&q, g_q);
    cudaGetSymbolAddress((void**)&whi, g_whi);
    cudaGetSymbolAddress((void**)&wlo, g_wlo);

    SplitJobs J;
    const float* srcs[10] = {x0, x1, W1l_0, W1r_0, W2l_0, W2r_0, W1l_1, W1r_1, W2l_1, W2r_1};
    int counts[10] = {N_NODES * 128, N_NODES * 128,
                      32768, 32768, 32768, 32768, 32768, 32768, 32768, 32768};
    int cum = 0;
    for (int j = 0; j < 10; j++) {
        J.src[j] = srcs[j];
        J.f16[j] = nullptr;
        if (j == 0)      { J.hi[j] = xhi; J.lo[j] = xlo; J.f16[j] = xh16; }
        else if (j == 1) { J.hi[j] = xhi + (size_t)N_NODES * 128;
                           J.lo[j] = xlo + (size_t)N_NODES * 128;
                           J.f16[j] = xh16 + (size_t)N_NODES * 128; }
        else             { J.hi[j] = whi + (j - 2) * 32768;
                           J.lo[j] = wlo + (j - 2) * 32768; }
        J.n4cum[j] = cum;
        cum += counts[j] / 4;
    }
    J.n4cum[10] = cum;
    split_all_kernel<<<(cum + 255) / 256, 256>>>(J);

    // ---- merged CSR (count zeroed by scan for next replay) ----
    hist_kernel<<<(ETOT + 255) / 256, 256>>>(ei0, ei1, count);
    scan_kernel<<<1, 1024>>>(count, row_start, cursor, NTOT);
    scatter_kernel<<<(ETOT + 255) / 256, 256>>>(ei0, ei1, cursor, srcsort);

    GemmW W1, W2;
    for (int g = 0; g < 2; g++) {
        for (int y = 0; y < 2; y++) {
            W1.b0hi[y][g] = whi + (4 * g + 0) * 32768; W1.b0lo[y][g] = wlo + (4 * g + 0) * 32768;
            W1.b1hi[y][g] = whi + (4 * g + 1) * 32768; W1.b1lo[y][g] = wlo + (4 * g + 1) * 32768;
        }
        W2.b0hi[0][g] = whi + (4 * g + 2) * 32768;       W2.b0lo[0][g] = wlo + (4 * g + 2) * 32768;
        W2.b1hi[0][g] = whi + (4 * g + 2) * 32768 + 128; W2.b1lo[0][g] = wlo + (4 * g + 2) * 32768 + 128;
        W2.b0hi[1][g] = whi + (4 * g + 3) * 32768;       W2.b0lo[1][g] = wlo + (4 * g + 3) * 32768;
        W2.b1hi[1][g] = whi + (4 * g + 3) * 32768 + 128; W2.b1lo[1][g] = wlo + (4 * g + 3) * 32768 + 128;
    }
    W1.bias[0] = b1_0; W1.bias[1] = b1_1;
    W2.bias[0] = b2_0; W2.bias[1] = b2_1;

    // ---- layer 1 ----
    aggregate1_kernel<<<NTOT / 4, 128>>>(xh16, row_start, srcsort, ahi, alo);
    {
        dim3 grid(M_TILES, 2, 2);
        sage_mma_kernel<128, 128, 128, 128, 128, 0><<<grid, 256, SMEM>>>(
            ahi, alo, xhi, xlo, W1, hhi, hlo, nullptr, nullptr);
    }
    // ---- layer 2 ----
    {
        dim3 grid(M_TILES, 2, 2);
        sage_mma_kernel<128, 128, 256, 256, 0, 1><<<grid, 256, SMEM>>>(
            hhi, hlo, hhi + 128, hlo + 128, W2, nullptr, nullptr, p, q);
    }
    agg_fuse2_kernel<<<NTOT / 4, 128>>>(p, q, row_start, srcsort, b2_0, b2_1, out);
}

// round 9
// speedup vs baseline: 1.1884x; 1.0713x over previous
#include <cuda_runtime.h>
#include <cuda_bf16.h>
#include <cuda_fp16.h>
#include <math.h>
#include <stdint.h>

#define N_NODES 50000
#define NTOT    (2 * N_NODES)
#define NEDGE   800000
#define ETOT    (2 * NEDGE)
#define M_TILES ((N_NODES + 127) / 128)   // 391 per graph
#define SCAN_BLOCKS ((NTOT + 1023) / 1024)

// ================= device scratch =================
__device__ int   g_count[NTOT];
__device__ int   g_row_start[NTOT + 1];
__device__ int   g_cursor[NTOT];
__device__ int   g_srcsort[ETOT];
__device__ int   g_btot[SCAN_BLOCKS];
__device__ int   g_boff[SCAN_BLOCKS];
__device__ __nv_bfloat16 g_xhi[(size_t)NTOT * 128];
__device__ __nv_bfloat16 g_xlo[(size_t)NTOT * 128];
__device__ __half        g_xh16[(size_t)NTOT * 128];
__device__ __nv_bfloat16 g_hhi[(size_t)NTOT * 256];
__device__ __nv_bfloat16 g_hlo[(size_t)NTOT * 256];
__device__ __nv_bfloat16 g_ahi[(size_t)NTOT * 128];
__device__ __nv_bfloat16 g_alo[(size_t)NTOT * 128];
__device__ __half g_v[(size_t)NTOT * 256];
__device__ __half g_p[(size_t)NTOT * 128];
__device__ float  g_q[(size_t)NTOT * 128];
__device__ __nv_bfloat16 g_whi[8 * 32768];
__device__ __nv_bfloat16 g_wlo[8 * 32768];

// ================= helpers =================
__device__ __forceinline__ uint32_t smem_u32(const void* p) {
    uint32_t a;
    asm("{ .reg .u64 t; cvta.to.shared.u64 t, %1; cvt.u32.u64 %0, t; }" : "=r"(a) : "l"(p));
    return a;
}
__device__ __forceinline__ void cp_async16(uint32_t dst, const void* src, bool valid) {
    if (valid) {
        asm volatile("cp.async.cg.shared.global [%0], [%1], 16;" :: "r"(dst), "l"(src));
    } else {
        asm volatile("cp.async.cg.shared.global [%0], [%1], 16, %2;"
                     :: "r"(dst), "l"(src), "r"(0u));
    }
}
#define CP_COMMIT()  asm volatile("cp.async.commit_group;" ::: "memory")
#define CP_WAIT1()   asm volatile("cp.async.wait_group 1;" ::: "memory")

__device__ __forceinline__ void ldsm4(uint32_t* r, uint32_t addr) {
    asm volatile("ldmatrix.sync.aligned.m8n8.x4.shared.b16 {%0,%1,%2,%3}, [%4];"
                 : "=r"(r[0]), "=r"(r[1]), "=r"(r[2]), "=r"(r[3]) : "r"(addr));
}
__device__ __forceinline__ void mma16816(float* d, const uint32_t* a, const uint32_t* b) {
    asm volatile(
        "mma.sync.aligned.m16n8k16.row.col.f32.bf16.bf16.f32 "
        "{%0,%1,%2,%3}, {%4,%5,%6,%7}, {%8,%9}, {%0,%1,%2,%3};"
        : "+f"(d[0]), "+f"(d[1]), "+f"(d[2]), "+f"(d[3])
        : "r"(a[0]), "r"(a[1]), "r"(a[2]), "r"(a[3]), "r"(b[0]), "r"(b[1]));
}

__device__ __forceinline__ float fast_tanh(float x) {
    float e = __expf(2.0f * x);
    return 1.0f - __fdividef(2.0f, e + 1.0f);
}

// ================= upfront split of all fp32 inputs =================
struct SplitJobs {
    const float* src[10];
    __nv_bfloat16* hi[10];
    __nv_bfloat16* lo[10];
    __half* f16[10];
    int n4cum[11];
};

__global__ void split_all_kernel(SplitJobs J) {
    int f = blockIdx.x * blockDim.x + threadIdx.x;
    if (f >= J.n4cum[10]) return;
    int j = 0;
#pragma unroll
    for (int t = 0; t < 10; t++)
        if (f >= J.n4cum[t + 1]) j = t + 1;
    int local = f - J.n4cum[j];
    float4 v = *(const float4*)(J.src[j] + 4 * (size_t)local);
    __nv_bfloat16 hx = __float2bfloat16(v.x);
    __nv_bfloat16 hy = __float2bfloat16(v.y);
    __nv_bfloat16 hz = __float2bfloat16(v.z);
    __nv_bfloat16 hw = __float2bfloat16(v.w);
    __nv_bfloat162 h01, h23, l01, l23;
    h01.x = hx; h01.y = hy; h23.x = hz; h23.y = hw;
    l01.x = __float2bfloat16(v.x - __bfloat162float(hx));
    l01.y = __float2bfloat16(v.y - __bfloat162float(hy));
    l23.x = __float2bfloat16(v.z - __bfloat162float(hz));
    l23.y = __float2bfloat16(v.w - __bfloat162float(hw));
    *(__nv_bfloat162*)(J.hi[j] + 4 * (size_t)local) = h01;
    *(__nv_bfloat162*)(J.hi[j] + 4 * (size_t)local + 2) = h23;
    *(__nv_bfloat162*)(J.lo[j] + 4 * (size_t)local) = l01;
    *(__nv_bfloat162*)(J.lo[j] + 4 * (size_t)local + 2) = l23;
    if (J.f16[j]) {
        __half2 a = __floats2half2_rn(v.x, v.y);
        __half2 b = __floats2half2_rn(v.z, v.w);
        uint2 pk;
        pk.x = *(uint32_t*)&a;
        pk.y = *(uint32_t*)&b;
        *(uint2*)(J.f16[j] + 4 * (size_t)local) = pk;
    }
}

// ================= merged CSR build =================
__global__ void hist_kernel(const int* __restrict__ ei0, const int* __restrict__ ei1,
                            int* __restrict__ count) {
    int e = blockIdx.x * blockDim.x + threadIdx.x;
    if (e >= ETOT) return;
    int d;
    if (e < NEDGE) d = ei0[NEDGE + e];
    else           d = ei1[NEDGE + (e - NEDGE)] + N_NODES;
    atomicAdd(&count[d], 1);
}

// per-block exclusive scan; zeroes counts; writes block totals
__global__ void scan_part_kernel(int* __restrict__ counts, int* __restrict__ row_start,
                                 int* __restrict__ btot) {
    __shared__ int wsum[32];
    int tid = threadIdx.x, lane = tid & 31, w = tid >> 5;
    int i = blockIdx.x * 1024 + tid;
    int v = 0;
    if (i < NTOT) { v = counts[i]; counts[i] = 0; }
    int x = v;
#pragma unroll
    for (int off = 1; off < 32; off <<= 1) {
        int t = __shfl_up_sync(0xFFFFFFFFu, x, off);
        if (lane >= off) x += t;
    }
    if (lane == 31) wsum[w] = x;
    __syncthreads();
    if (w == 0) {
        int s = wsum[lane];
#pragma unroll
        for (int off = 1; off < 32; off <<= 1) {
            int t = __shfl_up_sync(0xFFFFFFFFu, s, off);
            if (lane >= off) s += t;
        }
        wsum[lane] = s;
    }
    __syncthreads();
    int excl = x - v + (w ? wsum[w - 1] : 0);
    if (i < NTOT) row_start[i] = excl;
    if (tid == 0) btot[blockIdx.x] = wsum[31];
}

__global__ void scan_tops_kernel(const int* __restrict__ btot, int* __restrict__ boff) {
    __shared__ int sh[128];
    int tid = threadIdx.x;
    int v = (tid < SCAN_BLOCKS) ? btot[tid] : 0;
    sh[tid] = v;
    __syncthreads();
    for (int off = 1; off < 128; off <<= 1) {
        int t = (tid >= off) ? sh[tid - off] : 0;
        __syncthreads();
        sh[tid] += t;
        __syncthreads();
    }
    if (tid < SCAN_BLOCKS) boff[tid] = sh[tid] - v;
}

__global__ void scan_add_kernel(const int* __restrict__ boff, int* __restrict__ row_start,
                                int* __restrict__ cursor) {
    int i = blockIdx.x * 1024 + threadIdx.x;
    if (i < NTOT) {
        int rs = row_start[i] + boff[blockIdx.x];
        row_start[i] = rs;
        cursor[i] = rs;
    }
    if (i == NTOT - 1) row_start[NTOT] = ETOT;
}

__global__ void scatter_kernel(const int* __restrict__ ei0, const int* __restrict__ ei1,
                               int* __restrict__ cursor, int* __restrict__ srcsort) {
    int e = blockIdx.x * blockDim.x + threadIdx.x;
    if (e >= ETOT) return;
    int s, d;
    if (e < NEDGE) {
        s = ei0[e];
        d = ei0[NEDGE + e];
    } else {
        int e1 = e - NEDGE;
        s = ei1[e1] + N_NODES;
        d = ei1[NEDGE + e1] + N_NODES;
    }
    int p = atomicAdd(&cursor[d], 1);
    srcsort[p] = s;
}

// ================= layer-1 mean aggregation: fp16 x gathers =================
__global__ void aggregate1_kernel(const __half* __restrict__ xh,
                                  const int* __restrict__ row_start,
                                  const int* __restrict__ srcsort,
                                  __nv_bfloat16* __restrict__ ohi,
                                  __nv_bfloat16* __restrict__ olo) {
    int local = threadIdx.x >> 5;
    int t4 = (threadIdx.x & 31) * 4;
    int node = blockIdx.x * 4 + local;
    int s0 = row_start[node];
    int s1 = row_start[node + 1];
    float a0 = 0.f, a1 = 0.f, a2 = 0.f, a3 = 0.f;
    int e = s0;
    for (; e + 2 <= s1; e += 2) {
        uint2 vA = *(const uint2*)(xh + (size_t)srcsort[e] * 128 + t4);
        uint2 vB = *(const uint2*)(xh + (size_t)srcsort[e + 1] * 128 + t4);
        float2 fA0 = __half22float2(*(__half2*)&vA.x);
        float2 fA1 = __half22float2(*(__half2*)&vA.y);
        float2 fB0 = __half22float2(*(__half2*)&vB.x);
        float2 fB1 = __half22float2(*(__half2*)&vB.y);
        a0 += fA0.x + fB0.x; a1 += fA0.y + fB0.y;
        a2 += fA1.x + fB1.x; a3 += fA1.y + fB1.y;
    }
    if (e < s1) {
        uint2 v = *(const uint2*)(xh + (size_t)srcsort[e] * 128 + t4);
        float2 f0 = __half22float2(*(__half2*)&v.x);
        float2 f1 = __half22float2(*(__half2*)&v.y);
        a0 += f0.x; a1 += f0.y; a2 += f1.x; a3 += f1.y;
    }
    float inv = 1.0f / (float)max(s1 - s0, 1);
    a0 *= inv; a1 *= inv; a2 *= inv; a3 *= inv;
    __nv_bfloat16 h0 = __float2bfloat16(a0);
    __nv_bfloat16 h1 = __float2bfloat16(a1);
    __nv_bfloat16 h2 = __float2bfloat16(a2);
    __nv_bfloat16 h3 = __float2bfloat16(a3);
    __nv_bfloat162 ph01, ph23, pl01, pl23;
    ph01.x = h0; ph01.y = h1; ph23.x = h2; ph23.y = h3;
    pl01.x = __float2bfloat16(a0 - __bfloat162float(h0));
    pl01.y = __float2bfloat16(a1 - __bfloat162float(h1));
    pl23.x = __float2bfloat16(a2 - __bfloat162float(h2));
    pl23.y = __float2bfloat16(a3 - __bfloat162float(h3));
    size_t ob = (size_t)node * 128 + t4;
    *(__nv_bfloat162*)(ohi + ob) = ph01;
    *(__nv_bfloat162*)(ohi + ob + 2) = ph23;
    *(__nv_bfloat162*)(olo + ob) = pl01;
    *(__nv_bfloat162*)(olo + ob + 2) = pl23;
}

// ================= layer-2 fused aggregation + epilogue =================
__global__ void agg_fuse2_kernel(const __half* __restrict__ p,
                                 const float* __restrict__ q,
                                 const int* __restrict__ row_start,
                                 const int* __restrict__ srcsort,
                                 const float* __restrict__ b2_0,
                                 const float* __restrict__ b2_1,
                                 float* __restrict__ out) {
    int local = threadIdx.x >> 5;
    int t4 = (threadIdx.x & 31) * 4;
    int node = blockIdx.x * 4 + local;
    int s0 = row_start[node];
    int s1 = row_start[node + 1];
    float a0 = 0.f, a1 = 0.f, a2 = 0.f, a3 = 0.f;
    int e = s0;
    for (; e + 2 <= s1; e += 2) {
        uint2 vA = *(const uint2*)(p + (size_t)srcsort[e] * 128 + t4);
        uint2 vB = *(const uint2*)(p + (size_t)srcsort[e + 1] * 128 + t4);
        float2 fA0 = __half22float2(*(__half2*)&vA.x);
        float2 fA1 = __half22float2(*(__half2*)&vA.y);
        float2 fB0 = __half22float2(*(__half2*)&vB.x);
        float2 fB1 = __half22float2(*(__half2*)&vB.y);
        a0 += fA0.x + fB0.x; a1 += fA0.y + fB0.y;
        a2 += fA1.x + fB1.x; a3 += fA1.y + fB1.y;
    }
    if (e < s1) {
        uint2 v = *(const uint2*)(p + (size_t)srcsort[e] * 128 + t4);
        float2 f0 = __half22float2(*(__half2*)&v.x);
        float2 f1 = __half22float2(*(__half2*)&v.y);
        a0 += f0.x; a1 += f0.y; a2 += f1.x; a3 += f1.y;
    }
    float inv = 1.0f / (float)max(s1 - s0, 1);
    const float* b = (node < N_NODES) ? b2_0 : b2_1;
    float4 qq = *(const float4*)(q + (size_t)node * 128 + t4);
    float4 bb = *(const float4*)(b + t4);
    float4 o;
    o.x = fast_tanh(a0 * inv + qq.x + bb.x);
    o.y = fast_tanh(a1 * inv + qq.y + bb.y);
    o.z = fast_tanh(a2 * inv + qq.z + bb.z);
    o.w = fast_tanh(a3 * inv + qq.w + bb.w);
    *(float4*)(out + (size_t)node * 128 + t4) = o;
}

// ================= mma.sync split-bf16 GEMM (batched graphs) =================
struct GemmW {
    const __nv_bfloat16* b0hi[2][2];
    const __nv_bfloat16* b0lo[2][2];
    const __nv_bfloat16* b1hi[2][2];
    const __nv_bfloat16* b1lo[2][2];
    const float* bias[2];
};

// MODE 1: layer2 p/q — y==0: p(half)=acc @ row*128; y==1: q(float)=acc @ row*128
// MODE 2: v = x@W1r^T — v(half) = acc @ row*256 + n0 + col (no bias)
// MODE 3: u fused — h = tanh(acc + v + bias) -> bf16 hi/lo @ row*256 + n0 + col
template <int NT, int KHALF, int ASTRIDE, int BSTRIDE, int BOFF, int MODE>
__global__ void __launch_bounds__(256, 2)
sage_mma_kernel(const __nv_bfloat16* __restrict__ a0hi, const __nv_bfloat16* __restrict__ a0lo,
                const __nv_bfloat16* __restrict__ a1hi, const __nv_bfloat16* __restrict__ a1lo,
                GemmW W,
                __nv_bfloat16* __restrict__ ohi, __nv_bfloat16* __restrict__ olo,
                __half* __restrict__ op, float* __restrict__ oq,
                const __half* __restrict__ vin) {
    constexpr int NC = 2 * KHALF / 32;
    constexpr int MATB_A = 10240;
    constexpr int MATB_B = NT * 80;
    constexpr int STAGE = 2 * MATB_A + 2 * MATB_B;
    constexpr int WARPS_M = 2;
    constexpr int ROWS_W = 64;
    constexpr int MT = 4;
    constexpr int ITERS = (256 + 2 * NT) * 4 / 256;

    extern __shared__ char smem[];
    uint32_t sb = smem_u32(smem);

    int tid = threadIdx.x;
    int wid = tid >> 5;
    int lane = tid & 31;
    int wm = wid % WARPS_M;
    int wn = wid / WARPS_M;
    int y = blockIdx.y;
    int g = blockIdx.z;
    int m0 = g * N_NODES + blockIdx.x * 128;
    int Mlim = (g + 1) * N_NODES;
    int n0 = y * NT;
    int bn0 = y * BOFF;

    const __nv_bfloat16* B0h = W.b0hi[y][g];
    const __nv_bfloat16* B0l = W.b0lo[y][g];
    const __nv_bfloat16* B1h = W.b1hi[y][g];
    const __nv_bfloat16* B1l = W.b1lo[y][g];

    auto issue = [&](int c) {
        int half = (c * 32 >= KHALF) ? 1 : 0;
        int kh0 = c * 32 - half * KHALF;
        const __nv_bfloat16* Ah = half ? a1hi : a0hi;
        const __nv_bfloat16* Al = half ? a1lo : a0lo;
        const __nv_bfloat16* Bh = half ? B1h : B0h;
        const __nv_bfloat16* Bl = half ? B1l : B0l;
        uint32_t st = sb + (c & 1) * STAGE;
#pragma unroll
        for (int i = 0; i < ITERS; i++) {
            int idx = i * 256 + tid;
            int ch = idx & 3;
            if (idx < 1024) {
                int mat = idx >> 9;
                int r = (idx >> 2) & 127;
                int m = m0 + r;
                bool valid = (m < Mlim);
                const __nv_bfloat16* src = (mat ? Al : Ah);
                const __nv_bfloat16* pp = src + (size_t)(valid ? m : 0) * ASTRIDE + kh0 + ch * 8;
                cp_async16(st + mat * MATB_A + r * 80 + ch * 16, pp, valid);
            } else {
                int idx2 = idx - 1024;
                int matb = idx2 / (NT * 4);
                int r = (idx2 >> 2) % NT;
                const __nv_bfloat16* src = (matb ? Bl : Bh);
                cp_async16(st + 2 * MATB_A + matb * MATB_B + r * 80 + ch * 16,
                           src + (size_t)(bn0 + r) * BSTRIDE + kh0 + ch * 8, true);
            }
        }
    };

    float acc[MT][4][4];
#pragma unroll
    for (int i = 0; i < MT; i++)
#pragma unroll
        for (int j = 0; j < 4; j++)
#pragma unroll
            for (int k = 0; k < 4; k++) acc[i][j][k] = 0.f;

    issue(0); CP_COMMIT();
    if (NC > 1) issue(1);
    CP_COMMIT();

    uint32_t a_row = (uint32_t)(wm * ROWS_W + (lane & 15)) * 80 + (lane >> 4) * 16;
    uint32_t b_row = (uint32_t)(wn * 32 + (lane & 7) + ((lane >> 4) << 3)) * 80 +
                     ((lane >> 3) & 1) * 16;

    for (int c = 0; c < NC; c++) {
        CP_WAIT1();
        __syncthreads();
        uint32_t st = sb + (c & 1) * STAGE;
#pragma unroll
        for (int ks = 0; ks < 2; ks++) {
            uint32_t ko = ks * 32;
            uint32_t Ahf[MT][4], Alf[MT][4], Bhf[2][4], Blf[2][4];
#pragma unroll
            for (int mt = 0; mt < MT; mt++) {
                uint32_t ar = st + a_row + (uint32_t)mt * (16 * 80) + ko;
                ldsm4(Ahf[mt], ar);
                ldsm4(Alf[mt], ar + MATB_A);
            }
#pragma unroll
            for (int nt2 = 0; nt2 < 2; nt2++) {
                uint32_t br = st + 2 * MATB_A + b_row + (uint32_t)nt2 * (16 * 80) + ko;
                ldsm4(Bhf[nt2], br);
                ldsm4(Blf[nt2], br + MATB_B);
            }
#pragma unroll
            for (int mt = 0; mt < MT; mt++) {
#pragma unroll
                for (int nt = 0; nt < 4; nt++) {
                    const uint32_t* bh = &Bhf[nt >> 1][(nt & 1) * 2];
                    const uint32_t* bl = &Blf[nt >> 1][(nt & 1) * 2];
                    mma16816(acc[mt][nt], Ahf[mt], bh);
                    mma16816(acc[mt][nt], Ahf[mt], bl);
                    mma16816(acc[mt][nt], Alf[mt], bh);
                }
            }
        }
        __syncthreads();
        if (c + 2 < NC) issue(c + 2);
        CP_COMMIT();
    }

    int gq = lane >> 2, t4 = lane & 3;
    const float* bias = (MODE == 3) ? W.bias[g] : nullptr;
#pragma unroll
    for (int mt = 0; mt < MT; mt++) {
#pragma unroll
        for (int nt = 0; nt < 4; nt++) {
            int col = wn * 32 + nt * 8 + 2 * t4;       // [0,128)
            float b0 = (MODE == 3) ? bias[n0 + col] : 0.f;
            float b1 = (MODE == 3) ? bias[n0 + col + 1] : 0.f;
#pragma unroll
            for (int hrow = 0; hrow < 2; hrow++) {
                int row = m0 + wm * ROWS_W + mt * 16 + gq + hrow * 8;
                if (row < Mlim) {
                    float v0 = acc[mt][nt][2 * hrow + 0];
                    float v1 = acc[mt][nt][2 * hrow + 1];
                    if (MODE == 1) {
                        size_t ob = (size_t)row * 128 + col;
                        if (y == 0) {
                            *(__half2*)(op + ob) = __floats2half2_rn(v0, v1);
                        } else {
                            float2 o; o.x = v0; o.y = v1;
                            *(float2*)(oq + ob) = o;
                        }
                    } else if (MODE == 2) {
                        size_t ob = (size_t)row * 256 + n0 + col;
                        *(__half2*)(op + ob) = __floats2half2_rn(v0, v1);
                    } else {  // MODE == 3
                        size_t ob = (size_t)row * 256 + n0 + col;
                        float2 vv = __half22float2(*(const __half2*)(vin + ob));
                        v0 = fast_tanh(v0 + vv.x + b0);
                        v1 = fast_tanh(v1 + vv.y + b1);
                        __nv_bfloat16 h0 = __float2bfloat16(v0);
                        __nv_bfloat16 h1 = __float2bfloat16(v1);
                        __nv_bfloat162 ph; ph.x = h0; ph.y = h1;
                        __nv_bfloat162 pl;
                        pl.x = __float2bfloat16(v0 - __bfloat162float(h0));
                        pl.y = __float2bfloat16(v1 - __bfloat162float(h1));
                        *(__nv_bfloat162*)(ohi + ob) = ph;
                        *(__nv_bfloat162*)(olo + ob) = pl;
                    }
                }
            }
        }
    }
}

// ================= host =================
extern "C" void kernel_launch(void* const* d_in, const int* in_sizes, int n_in,
                              void* d_out, int out_size) {
    (void)in_sizes; (void)n_in; (void)out_size;

    const float* x0  = (const float*)d_in[0];
    const float* x1  = (const float*)d_in[1];
    const int*   ei0 = (const int*)d_in[2];
    const int*   ei1 = (const int*)d_in[3];
    const float* W1l_0 = (const float*)d_in[4];
    const float* b1_0  = (const float*)d_in[5];
    const float* W1r_0 = (const float*)d_in[6];
    const float* W2l_0 = (const float*)d_in[7];
    const float* b2_0  = (const float*)d_in[8];
    const float* W2r_0 = (const float*)d_in[9];
    const float* W1l_1 = (const float*)d_in[10];
    const float* b1_1  = (const float*)d_in[11];
    const float* W1r_1 = (const float*)d_in[12];
    const float* W2l_1 = (const float*)d_in[13];
    const float* b2_1  = (const float*)d_in[14];
    const float* W2r_1 = (const float*)d_in[15];
    float* out = (float*)d_out;

    constexpr int SMEM = 2 * (2 * 10240 + 2 * 128 * 80);  // 81920
    cudaFuncSetAttribute((const void*)sage_mma_kernel<128, 128, 256, 256, 0, 1>,
                         cudaFuncAttributeMaxDynamicSharedMemorySize, SMEM);
    cudaFuncSetAttribute((const void*)sage_mma_kernel<128, 64, 128, 128, 128, 2>,
                         cudaFuncAttributeMaxDynamicSharedMemorySize, SMEM);
    cudaFuncSetAttribute((const void*)sage_mma_kernel<128, 64, 128, 128, 128, 3>,
                         cudaFuncAttributeMaxDynamicSharedMemorySize, SMEM);

    int *count, *row_start, *cursor, *srcsort, *btot, *boff;
    __nv_bfloat16 *xhi, *xlo, *hhi, *hlo, *ahi, *alo, *whi, *wlo;
    __half *xh16, *p, *v;
    float *q;
    cudaGetSymbolAddress((void**)&count, g_count);
    cudaGetSymbolAddress((void**)&row_start, g_row_start);
    cudaGetSymbolAddress((void**)&cursor, g_cursor);
    cudaGetSymbolAddress((void**)&srcsort, g_srcsort);
    cudaGetSymbolAddress((void**)&btot, g_btot);
    cudaGetSymbolAddress((void**)&boff, g_boff);
    cudaGetSymbolAddress((void**)&xhi, g_xhi);
    cudaGetSymbolAddress((void**)&xlo, g_xlo);
    cudaGetSymbolAddress((void**)&xh16, g_xh16);
    cudaGetSymbolAddress((void**)&hhi, g_hhi);
    cudaGetSymbolAddress((void**)&hlo, g_hlo);
    cudaGetSymbolAddress((void**)&ahi, g_ahi);
    cudaGetSymbolAddress((void**)&alo, g_alo);
    cudaGetSymbolAddress((void**)&v, g_v);
    cudaGetSymbolAddress((void**)&p, g_p);
    cudaGetSymbolAddress((void**)&q, g_q);
    cudaGetSymbolAddress((void**)&whi, g_whi);
    cudaGetSymbolAddress((void**)&wlo, g_wlo);

    SplitJobs J;
    const float* srcs[10] = {x0, x1, W1l_0, W1r_0, W2l_0, W2r_0, W1l_1, W1r_1, W2l_1, W2r_1};
    int counts[10] = {N_NODES * 128, N_NODES * 128,
                      32768, 32768, 32768, 32768, 32768, 32768, 32768, 32768};
    int cum = 0;
    for (int j = 0; j < 10; j++) {
        J.src[j] = srcs[j];
        J.f16[j] = nullptr;
        if (j == 0)      { J.hi[j] = xhi; J.lo[j] = xlo; J.f16[j] = xh16; }
        else if (j == 1) { J.hi[j] = xhi + (size_t)N_NODES * 128;
                           J.lo[j] = xlo + (size_t)N_NODES * 128;
                           J.f16[j] = xh16 + (size_t)N_NODES * 128; }
        else             { J.hi[j] = whi + (j - 2) * 32768;
                           J.lo[j] = wlo + (j - 2) * 32768; }
        J.n4cum[j] = cum;
        cum += counts[j] / 4;
    }
    J.n4cum[10] = cum;

    // weight slot indices: W1l=4g+0, W1r=4g+1, W2l=4g+2, W2r=4g+3
    GemmW Wv, Wu, W2;
    for (int g = 0; g < 2; g++) {
        for (int y = 0; y < 2; y++) {
            // v-GEMM: B = W1r [256,128]; y selects row half via BOFF; K halves = cols 0..63/64..127
            Wv.b0hi[y][g] = whi + (4 * g + 1) * 32768;      Wv.b0lo[y][g] = wlo + (4 * g + 1) * 32768;
            Wv.b1hi[y][g] = whi + (4 * g + 1) * 32768 + 64; Wv.b1lo[y][g] = wlo + (4 * g + 1) * 32768 + 64;
            // u-GEMM: B = W1l
            Wu.b0hi[y][g] = whi + (4 * g + 0) * 32768;      Wu.b0lo[y][g] = wlo + (4 * g + 0) * 32768;
            Wu.b1hi[y][g] = whi + (4 * g + 0) * 32768 + 64; Wu.b1lo[y][g] = wlo + (4 * g + 0) * 32768 + 64;
        }
        W2.b0hi[0][g] = whi + (4 * g + 2) * 32768;       W2.b0lo[0][g] = wlo + (4 * g + 2) * 32768;
        W2.b1hi[0][g] = whi + (4 * g + 2) * 32768 + 128; W2.b1lo[0][g] = wlo + (4 * g + 2) * 32768 + 128;
        W2.b0hi[1][g] = whi + (4 * g + 3) * 32768;       W2.b0lo[1][g] = wlo + (4 * g + 3) * 32768;
        W2.b1hi[1][g] = whi + (4 * g + 3) * 32768 + 128; W2.b1lo[1][g] = wlo + (4 * g + 3) * 32768 + 128;
    }
    Wu.bias[0] = b1_0; Wu.bias[1] = b1_1;
    Wv.bias[0] = nullptr; Wv.bias[1] = nullptr;
    W2.bias[0] = nullptr; W2.bias[1] = nullptr;

    cudaStream_t s2;
    cudaStreamCreateWithFlags(&s2, cudaStreamNonBlocking);
    cudaEvent_t evSplit, evV;
    cudaEventCreateWithFlags(&evSplit, cudaEventDisableTiming);
    cudaEventCreateWithFlags(&evV, cudaEventDisableTiming);

    // main: split, then CSR chain + agg1 (memory-bound)
    split_all_kernel<<<(cum + 255) / 256, 256>>>(J);
    cudaEventRecord(evSplit, 0);

    // s2: v = x @ W1r^T (tensor-bound) overlapping the CSR/agg phase
    cudaStreamWaitEvent(s2, evSplit, 0);
    {
        dim3 grid(M_TILES, 2, 2);
        sage_mma_kernel<128, 64, 128, 128, 128, 2><<<grid, 256, SMEM, s2>>>(
            xhi, xlo, xhi + 64, xlo + 64, Wv, nullptr, nullptr, v, nullptr, nullptr);
    }
    cudaEventRecord(evV, s2);

    hist_kernel<<<(ETOT + 255) / 256, 256>>>(ei0, ei1, count);
    scan_part_kernel<<<SCAN_BLOCKS, 1024>>>(count, row_start, btot);
    scan_tops_kernel<<<1, 128>>>(btot, boff);
    scan_add_kernel<<<SCAN_BLOCKS, 1024>>>(boff, row_start, cursor);
    scatter_kernel<<<(ETOT + 255) / 256, 256>>>(ei0, ei1, cursor, srcsort);
    aggregate1_kernel<<<NTOT / 4, 128>>>(xh16, row_start, srcsort, ahi, alo);

    cudaStreamWaitEvent(0, evV, 0);

    // u-GEMM: h = tanh(agg @ W1l^T + v + b1), split-stored
    {
        dim3 grid(M_TILES, 2, 2);
        sage_mma_kernel<128, 64, 128, 128, 128, 3><<<grid, 256, SMEM>>>(
            ahi, alo, ahi + 64, alo + 64, Wu, hhi, hlo, nullptr, nullptr, v);
    }
    // layer 2: [p|q] = h @ [W2l^T | W2r^T]
    {
        dim3 grid(M_TILES, 2, 2);
        sage_mma_kernel<128, 128, 256, 256, 0, 1><<<grid, 256, SMEM>>>(
            hhi, hlo, hhi + 128, hlo + 128, W2, nullptr, nullptr, p, q, nullptr);
    }
    agg_fuse2_kernel<<<NTOT / 4, 128>>>(p, q, row_start, srcsort, b2_0, b2_1, out);

    cudaEventDestroy(evSplit);
    cudaEventDestroy(evV);
    cudaStreamDestroy(s2);
}

// round 10
// speedup vs baseline: 1.6498x; 1.3882x over previous
#include <cuda_runtime.h>
#include <cuda_fp16.h>
#include <math.h>
#include <stdint.h>

#define N_NODES 50000
#define NTOT    (2 * N_NODES)
#define NEDGE   800000
#define ETOT    (2 * NEDGE)
#define M_TILES ((N_NODES + 127) / 128)   // 391 per graph
#define SCAN_BLOCKS ((NTOT + 1023) / 1024)

// ================= device scratch =================
__device__ int   g_count[NTOT];
__device__ int   g_row_start[NTOT + 1];
__device__ int   g_cursor[NTOT];
__device__ int   g_srcsort[ETOT];
__device__ int   g_btot[SCAN_BLOCKS];
__device__ int   g_boff[SCAN_BLOCKS];
__device__ __half g_xh16[(size_t)NTOT * 128];
__device__ __half g_af16[(size_t)NTOT * 128];
__device__ __half g_h16[(size_t)NTOT * 256];
__device__ __half g_v[(size_t)NTOT * 256];
__device__ __half g_p[(size_t)NTOT * 128];
__device__ float  g_q[(size_t)NTOT * 128];
__device__ __half g_wf16[8 * 32768];

// ================= helpers =================
__device__ __forceinline__ uint32_t smem_u32(const void* p) {
    uint32_t a;
    asm("{ .reg .u64 t; cvta.to.shared.u64 t, %1; cvt.u32.u64 %0, t; }" : "=r"(a) : "l"(p));
    return a;
}
__device__ __forceinline__ void cp_async16(uint32_t dst, const void* src, bool valid) {
    if (valid) {
        asm volatile("cp.async.cg.shared.global [%0], [%1], 16;" :: "r"(dst), "l"(src));
    } else {
        asm volatile("cp.async.cg.shared.global [%0], [%1], 16, %2;"
                     :: "r"(dst), "l"(src), "r"(0u));
    }
}
#define CP_COMMIT()  asm volatile("cp.async.commit_group;" ::: "memory")
#define CP_WAIT1()   asm volatile("cp.async.wait_group 1;" ::: "memory")

__device__ __forceinline__ void ldsm4(uint32_t* r, uint32_t addr) {
    asm volatile("ldmatrix.sync.aligned.m8n8.x4.shared.b16 {%0,%1,%2,%3}, [%4];"
                 : "=r"(r[0]), "=r"(r[1]), "=r"(r[2]), "=r"(r[3]) : "r"(addr));
}
__device__ __forceinline__ void mma16816f16(float* d, const uint32_t* a, const uint32_t* b) {
    asm volatile(
        "mma.sync.aligned.m16n8k16.row.col.f32.f16.f16.f32 "
        "{%0,%1,%2,%3}, {%4,%5,%6,%7}, {%8,%9}, {%0,%1,%2,%3};"
        : "+f"(d[0]), "+f"(d[1]), "+f"(d[2]), "+f"(d[3])
        : "r"(a[0]), "r"(a[1]), "r"(a[2]), "r"(a[3]), "r"(b[0]), "r"(b[1]));
}

__device__ __forceinline__ float fast_tanh(float x) {
    float e = __expf(2.0f * x);
    return 1.0f - __fdividef(2.0f, e + 1.0f);
}

// ================= upfront fp32 -> fp16 conversion =================
struct SplitJobs {
    const float* src[10];
    __half* f16[10];
    int n4cum[11];
};

__global__ void split_all_kernel(SplitJobs J) {
    int f = blockIdx.x * blockDim.x + threadIdx.x;
    if (f >= J.n4cum[10]) return;
    int j = 0;
#pragma unroll
    for (int t = 0; t < 10; t++)
        if (f >= J.n4cum[t + 1]) j = t + 1;
    int local = f - J.n4cum[j];
    float4 v = *(const float4*)(J.src[j] + 4 * (size_t)local);
    __half2 a = __floats2half2_rn(v.x, v.y);
    __half2 b = __floats2half2_rn(v.z, v.w);
    uint2 pk;
    pk.x = *(uint32_t*)&a;
    pk.y = *(uint32_t*)&b;
    *(uint2*)(J.f16[j] + 4 * (size_t)local) = pk;
}

// ================= merged CSR build =================
__global__ void hist_kernel(const int* __restrict__ ei0, const int* __restrict__ ei1,
                            int* __restrict__ count) {
    int e = blockIdx.x * blockDim.x + threadIdx.x;
    if (e >= ETOT) return;
    int d;
    if (e < NEDGE) d = ei0[NEDGE + e];
    else           d = ei1[NEDGE + (e - NEDGE)] + N_NODES;
    atomicAdd(&count[d], 1);
}

__global__ void scan_part_kernel(int* __restrict__ counts, int* __restrict__ row_start,
                                 int* __restrict__ btot) {
    __shared__ int wsum[32];
    int tid = threadIdx.x, lane = tid & 31, w = tid >> 5;
    int i = blockIdx.x * 1024 + tid;
    int v = 0;
    if (i < NTOT) { v = counts[i]; counts[i] = 0; }
    int x = v;
#pragma unroll
    for (int off = 1; off < 32; off <<= 1) {
        int t = __shfl_up_sync(0xFFFFFFFFu, x, off);
        if (lane >= off) x += t;
    }
    if (lane == 31) wsum[w] = x;
    __syncthreads();
    if (w == 0) {
        int s = wsum[lane];
#pragma unroll
        for (int off = 1; off < 32; off <<= 1) {
            int t = __shfl_up_sync(0xFFFFFFFFu, s, off);
            if (lane >= off) s += t;
        }
        wsum[lane] = s;
    }
    __syncthreads();
    int excl = x - v + (w ? wsum[w - 1] : 0);
    if (i < NTOT) row_start[i] = excl;
    if (tid == 0) btot[blockIdx.x] = wsum[31];
}

__global__ void scan_tops_kernel(const int* __restrict__ btot, int* __restrict__ boff) {
    __shared__ int sh[128];
    int tid = threadIdx.x;
    int v = (tid < SCAN_BLOCKS) ? btot[tid] : 0;
    sh[tid] = v;
    __syncthreads();
    for (int off = 1; off < 128; off <<= 1) {
        int t = (tid >= off) ? sh[tid - off] : 0;
        __syncthreads();
        sh[tid] += t;
        __syncthreads();
    }
    if (tid < SCAN_BLOCKS) boff[tid] = sh[tid] - v;
}

__global__ void scan_add_kernel(const int* __restrict__ boff, int* __restrict__ row_start,
                                int* __restrict__ cursor) {
    int i = blockIdx.x * 1024 + threadIdx.x;
    if (i < NTOT) {
        int rs = row_start[i] + boff[blockIdx.x];
        row_start[i] = rs;
        cursor[i] = rs;
    }
    if (i == NTOT - 1) row_start[NTOT] = ETOT;
}

__global__ void scatter_kernel(const int* __restrict__ ei0, const int* __restrict__ ei1,
                               int* __restrict__ cursor, int* __restrict__ srcsort) {
    int e = blockIdx.x * blockDim.x + threadIdx.x;
    if (e >= ETOT) return;
    int s, d;
    if (e < NEDGE) {
        s = ei0[e];
        d = ei0[NEDGE + e];
    } else {
        int e1 = e - NEDGE;
        s = ei1[e1] + N_NODES;
        d = ei1[NEDGE + e1] + N_NODES;
    }
    int p = atomicAdd(&cursor[d], 1);
    srcsort[p] = s;
}

// ================= layer-1 mean aggregation: fp16 -> fp16 =================
__global__ void aggregate1_kernel(const __half* __restrict__ xh,
                                  const int* __restrict__ row_start,
                                  const int* __restrict__ srcsort,
                                  __half* __restrict__ oa) {
    int local = threadIdx.x >> 5;
    int t4 = (threadIdx.x & 31) * 4;
    int node = blockIdx.x * 4 + local;
    int s0 = row_start[node];
    int s1 = row_start[node + 1];
    float a0 = 0.f, a1 = 0.f, a2 = 0.f, a3 = 0.f;
    int e = s0;
    for (; e + 2 <= s1; e += 2) {
        uint2 vA = *(const uint2*)(xh + (size_t)srcsort[e] * 128 + t4);
        uint2 vB = *(const uint2*)(xh + (size_t)srcsort[e + 1] * 128 + t4);
        float2 fA0 = __half22float2(*(__half2*)&vA.x);
        float2 fA1 = __half22float2(*(__half2*)&vA.y);
        float2 fB0 = __half22float2(*(__half2*)&vB.x);
        float2 fB1 = __half22float2(*(__half2*)&vB.y);
        a0 += fA0.x + fB0.x; a1 += fA0.y + fB0.y;
        a2 += fA1.x + fB1.x; a3 += fA1.y + fB1.y;
    }
    if (e < s1) {
        uint2 v = *(const uint2*)(xh + (size_t)srcsort[e] * 128 + t4);
        float2 f0 = __half22float2(*(__half2*)&v.x);
        float2 f1 = __half22float2(*(__half2*)&v.y);
        a0 += f0.x; a1 += f0.y; a2 += f1.x; a3 += f1.y;
    }
    float inv = 1.0f / (float)max(s1 - s0, 1);
    __half2 h01 = __floats2half2_rn(a0 * inv, a1 * inv);
    __half2 h23 = __floats2half2_rn(a2 * inv, a3 * inv);
    uint2 pk;
    pk.x = *(uint32_t*)&h01;
    pk.y = *(uint32_t*)&h23;
    *(uint2*)(oa + (size_t)node * 128 + t4) = pk;
}

// ================= layer-2 fused aggregation + epilogue =================
__global__ void agg_fuse2_kernel(const __half* __restrict__ p,
                                 const float* __restrict__ q,
                                 const int* __restrict__ row_start,
                                 const int* __restrict__ srcsort,
                                 const float* __restrict__ b2_0,
                                 const float* __restrict__ b2_1,
                                 float* __restrict__ out) {
    int local = threadIdx.x >> 5;
    int t4 = (threadIdx.x & 31) * 4;
    int node = blockIdx.x * 4 + local;
    int s0 = row_start[node];
    int s1 = row_start[node + 1];
    float a0 = 0.f, a1 = 0.f, a2 = 0.f, a3 = 0.f;
    int e = s0;
    for (; e + 2 <= s1; e += 2) {
        uint2 vA = *(const uint2*)(p + (size_t)srcsort[e] * 128 + t4);
        uint2 vB = *(const uint2*)(p + (size_t)srcsort[e + 1] * 128 + t4);
        float2 fA0 = __half22float2(*(__half2*)&vA.x);
        float2 fA1 = __half22float2(*(__half2*)&vA.y);
        float2 fB0 = __half22float2(*(__half2*)&vB.x);
        float2 fB1 = __half22float2(*(__half2*)&vB.y);
        a0 += fA0.x + fB0.x; a1 += fA0.y + fB0.y;
        a2 += fA1.x + fB1.x; a3 += fA1.y + fB1.y;
    }
    if (e < s1) {
        uint2 v = *(const uint2*)(p + (size_t)srcsort[e] * 128 + t4);
        float2 f0 = __half22float2(*(__half2*)&v.x);
        float2 f1 = __half22float2(*(__half2*)&v.y);
        a0 += f0.x; a1 += f0.y; a2 += f1.x; a3 += f1.y;
    }
    float inv = 1.0f / (float)max(s1 - s0, 1);
    const float* b = (node < N_NODES) ? b2_0 : b2_1;
    float4 qq = *(const float4*)(q + (size_t)node * 128 + t4);
    float4 bb = *(const float4*)(b + t4);
    float4 o;
    o.x = fast_tanh(a0 * inv + qq.x + bb.x);
    o.y = fast_tanh(a1 * inv + qq.y + bb.y);
    o.z = fast_tanh(a2 * inv + qq.z + bb.z);
    o.w = fast_tanh(a3 * inv + qq.w + bb.w);
    *(float4*)(out + (size_t)node * 128 + t4) = o;
}

// ================= fp16 mma.sync GEMM (batched graphs) =================
struct GemmW {
    const __half* b0[2][2];   // [y][g] first K-half
    const __half* b1[2][2];   // [y][g] second K-half
    const float* bias[2];
};

// MODE 1: layer2 p/q — y==0: p(half)=acc @ row*128; y==1: q(float)=acc @ row*128
// MODE 2: v = x@W1r^T — v(half) = acc @ row*256 + n0 + col
// MODE 3: u fused — h(half) = tanh(acc + v + bias) @ row*256 + n0 + col
template <int KHALF, int ASTRIDE, int BSTRIDE, int BOFF, int MODE>
__global__ void __launch_bounds__(256, 2)
sage_mma_kernel(const __half* __restrict__ a0, const __half* __restrict__ a1,
                GemmW W,
                __half* __restrict__ oh, __half* __restrict__ op,
                float* __restrict__ oq, const __half* __restrict__ vin) {
    constexpr int NC = 2 * KHALF / 32;
    constexpr int MATB = 10240;              // 128 rows * 80 B
    constexpr int STAGE = 2 * MATB;          // A + B
    constexpr int MT = 4;

    extern __shared__ char smem[];
    uint32_t sb = smem_u32(smem);

    int tid = threadIdx.x;
    int wid = tid >> 5;
    int lane = tid & 31;
    int wm = wid & 1;            // 64-row half
    int wn = wid >> 1;           // 32-col quarter
    int y = blockIdx.y;
    int g = blockIdx.z;
    int m0 = g * N_NODES + blockIdx.x * 128;
    int Mlim = (g + 1) * N_NODES;
    int n0 = y * 128;
    int bn0 = y * BOFF;

    const __half* B0 = W.b0[y][g];
    const __half* B1 = W.b1[y][g];

    auto issue = [&](int c) {
        int half = (c * 32 >= KHALF) ? 1 : 0;
        int kh0 = c * 32 - half * KHALF;
        const __half* A = half ? a1 : a0;
        const __half* B = half ? B1 : B0;
        uint32_t st = sb + (c & 1) * STAGE;
#pragma unroll
        for (int i = 0; i < 4; i++) {
            int idx = i * 256 + tid;
            int r = idx >> 2;            // 0..255
            int ch = idx & 3;
            if (r < 128) {
                int m = m0 + r;
                bool valid = (m < Mlim);
                const __half* pp = A + (size_t)(valid ? m : 0) * ASTRIDE + kh0 + ch * 8;
                cp_async16(st + r * 80 + ch * 16, pp, valid);
            } else {
                int rl = r - 128;
                cp_async16(st + MATB + rl * 80 + ch * 16,
                           B + (size_t)(bn0 + rl) * BSTRIDE + kh0 + ch * 8, true);
            }
        }
    };

    float acc[MT][4][4];
#pragma unroll
    for (int i = 0; i < MT; i++)
#pragma unroll
        for (int j = 0; j < 4; j++)
#pragma unroll
            for (int k = 0; k < 4; k++) acc[i][j][k] = 0.f;

    issue(0); CP_COMMIT();
    issue(1); CP_COMMIT();

    uint32_t a_row = (uint32_t)(wm * 64 + (lane & 15)) * 80 + (lane >> 4) * 16;
    uint32_t b_row = (uint32_t)(wn * 32 + (lane & 7) + ((lane >> 4) << 3)) * 80 +
                     ((lane >> 3) & 1) * 16;

    for (int c = 0; c < NC; c++) {
        CP_WAIT1();
        __syncthreads();
        uint32_t st = sb + (c & 1) * STAGE;
#pragma unroll
        for (int ks = 0; ks < 2; ks++) {
            uint32_t ko = ks * 32;
            uint32_t Af[MT][4], Bf[2][4];
#pragma unroll
            for (int mt = 0; mt < MT; mt++)
                ldsm4(Af[mt], st + a_row + (uint32_t)mt * (16 * 80) + ko);
#pragma unroll
            for (int nt2 = 0; nt2 < 2; nt2++)
                ldsm4(Bf[nt2], st + MATB + b_row + (uint32_t)nt2 * (16 * 80) + ko);
#pragma unroll
            for (int mt = 0; mt < MT; mt++) {
#pragma unroll
                for (int nt = 0; nt < 4; nt++) {
                    mma16816f16(acc[mt][nt], Af[mt], &Bf[nt >> 1][(nt & 1) * 2]);
                }
            }
        }
        __syncthreads();
        if (c + 2 < NC) issue(c + 2);
        CP_COMMIT();
    }

    int gq = lane >> 2, t4 = lane & 3;
    const float* bias = (MODE == 3) ? W.bias[g] : nullptr;
#pragma unroll
    for (int mt = 0; mt < MT; mt++) {
#pragma unroll
        for (int nt = 0; nt < 4; nt++) {
            int col = wn * 32 + nt * 8 + 2 * t4;       // [0,128)
            float b0 = (MODE == 3) ? bias[n0 + col] : 0.f;
            float b1 = (MODE == 3) ? bias[n0 + col + 1] : 0.f;
#pragma unroll
            for (int hrow = 0; hrow < 2; hrow++) {
                int row = m0 + wm * 64 + mt * 16 + gq + hrow * 8;
                if (row < Mlim) {
                    float v0 = acc[mt][nt][2 * hrow + 0];
                    float v1 = acc[mt][nt][2 * hrow + 1];
                    if (MODE == 1) {
                        size_t ob = (size_t)row * 128 + col;
                        if (y == 0) {
                            *(__half2*)(op + ob) = __floats2half2_rn(v0, v1);
                        } else {
                            float2 o; o.x = v0; o.y = v1;
                            *(float2*)(oq + ob) = o;
                        }
                    } else if (MODE == 2) {
                        size_t ob = (size_t)row * 256 + n0 + col;
                        *(__half2*)(op + ob) = __floats2half2_rn(v0, v1);
                    } else {  // MODE 3
                        size_t ob = (size_t)row * 256 + n0 + col;
                        float2 vv = __half22float2(*(const __half2*)(vin + ob));
                        v0 = fast_tanh(v0 + vv.x + b0);
                        v1 = fast_tanh(v1 + vv.y + b1);
                        *(__half2*)(oh + ob) = __floats2half2_rn(v0, v1);
                    }
                }
            }
        }
    }
}

// ================= host =================
extern "C" void kernel_launch(void* const* d_in, const int* in_sizes, int n_in,
                              void* d_out, int out_size) {
    (void)in_sizes; (void)n_in; (void)out_size;

    const float* x0  = (const float*)d_in[0];
    const float* x1  = (const float*)d_in[1];
    const int*   ei0 = (const int*)d_in[2];
    const int*   ei1 = (const int*)d_in[3];
    const float* W1l_0 = (const float*)d_in[4];
    const float* b1_0  = (const float*)d_in[5];
    const float* W1r_0 = (const float*)d_in[6];
    const float* W2l_0 = (const float*)d_in[7];
    const float* b2_0  = (const float*)d_in[8];
    const float* W2r_0 = (const float*)d_in[9];
    const float* W1l_1 = (const float*)d_in[10];
    const float* b1_1  = (const float*)d_in[11];
    const float* W1r_1 = (const float*)d_in[12];
    const float* W2l_1 = (const float*)d_in[13];
    const float* b2_1  = (const float*)d_in[14];
    const float* W2r_1 = (const float*)d_in[15];
    float* out = (float*)d_out;

    constexpr int SMEM = 2 * 2 * 10240;  // 40960

    int *count, *row_start, *cursor, *srcsort, *btot, *boff;
    __half *xh16, *af16, *h16, *v, *p, *wf16;
    float *q;
    cudaGetSymbolAddress((void**)&count, g_count);
    cudaGetSymbolAddress((void**)&row_start, g_row_start);
    cudaGetSymbolAddress((void**)&cursor, g_cursor);
    cudaGetSymbolAddress((void**)&srcsort, g_srcsort);
    cudaGetSymbolAddress((void**)&btot, g_btot);
    cudaGetSymbolAddress((void**)&boff, g_boff);
    cudaGetSymbolAddress((void**)&xh16, g_xh16);
    cudaGetSymbolAddress((void**)&af16, g_af16);
    cudaGetSymbolAddress((void**)&h16, g_h16);
    cudaGetSymbolAddress((void**)&v, g_v);
    cudaGetSymbolAddress((void**)&p, g_p);
    cudaGetSymbolAddress((void**)&q, g_q);
    cudaGetSymbolAddress((void**)&wf16, g_wf16);

    SplitJobs J;
    const float* srcs[10] = {x0, x1, W1l_0, W1r_0, W2l_0, W2r_0, W1l_1, W1r_1, W2l_1, W2r_1};
    int counts[10] = {N_NODES * 128, N_NODES * 128,
                      32768, 32768, 32768, 32768, 32768, 32768, 32768, 32768};
    int cum = 0;
    for (int j = 0; j < 10; j++) {
        J.src[j] = srcs[j];
        if (j == 0)      J.f16[j] = xh16;
        else if (j == 1) J.f16[j] = xh16 + (size_t)N_NODES * 128;
        else             J.f16[j] = wf16 + (j - 2) * 32768;
        J.n4cum[j] = cum;
        cum += counts[j] / 4;
    }
    J.n4cum[10] = cum;

    // weight slots: W1l=4g+0, W1r=4g+1, W2l=4g+2, W2r=4g+3
    GemmW Wv, Wu, W2;
    for (int g = 0; g < 2; g++) {
        for (int y = 0; y < 2; y++) {
            Wv.b0[y][g] = wf16 + (4 * g + 1) * 32768;      // W1r [256,128]
            Wv.b1[y][g] = wf16 + (4 * g + 1) * 32768 + 64;
            Wu.b0[y][g] = wf16 + (4 * g + 0) * 32768;      // W1l [256,128]
            Wu.b1[y][g] = wf16 + (4 * g + 0) * 32768 + 64;
        }
        W2.b0[0][g] = wf16 + (4 * g + 2) * 32768;          // W2l [128,256]
        W2.b1[0][g] = wf16 + (4 * g + 2) * 32768 + 128;
        W2.b0[1][g] = wf16 + (4 * g + 3) * 32768;          // W2r [128,256]
        W2.b1[1][g] = wf16 + (4 * g + 3) * 32768 + 128;
    }
    Wu.bias[0] = b1_0; Wu.bias[1] = b1_1;
    Wv.bias[0] = nullptr; Wv.bias[1] = nullptr;
    W2.bias[0] = nullptr; W2.bias[1] = nullptr;

    cudaStream_t s2;
    cudaStreamCreateWithFlags(&s2, cudaStreamNonBlocking);
    cudaEvent_t evSplit, evV;
    cudaEventCreateWithFlags(&evSplit, cudaEventDisableTiming);
    cudaEventCreateWithFlags(&evV, cudaEventDisableTiming);

    // main: split, then CSR chain + agg1 (memory-bound)
    split_all_kernel<<<(cum + 255) / 256, 256>>>(J);
    cudaEventRecord(evSplit, 0);

    // s2: v = x @ W1r^T (tensor-bound) overlapping the CSR/agg phase
    cudaStreamWaitEvent(s2, evSplit, 0);
    {
        dim3 grid(M_TILES, 2, 2);
        sage_mma_kernel<64, 128, 128, 128, 2><<<grid, 256, SMEM, s2>>>(
            xh16, xh16 + 64, Wv, nullptr, v, nullptr, nullptr);
    }
    cudaEventRecord(evV, s2);

    hist_kernel<<<(ETOT + 255) / 256, 256>>>(ei0, ei1, count);
    scan_part_kernel<<<SCAN_BLOCKS, 1024>>>(count, row_start, btot);
    scan_tops_kernel<<<1, 128>>>(btot, boff);
    scan_add_kernel<<<SCAN_BLOCKS, 1024>>>(boff, row_start, cursor);
    scatter_kernel<<<(ETOT + 255) / 256, 256>>>(ei0, ei1, cursor, srcsort);
    aggregate1_kernel<<<NTOT / 4, 128>>>(xh16, row_start, srcsort, af16);

    cudaStreamWaitEvent(0, evV, 0);

    // u-GEMM: h = tanh(agg @ W1l^T + v + b1), fp16
    {
        dim3 grid(M_TILES, 2, 2);
        sage_mma_kernel<64, 128, 128, 128, 3><<<grid, 256, SMEM>>>(
            af16, af16 + 64, Wu, h16, nullptr, nullptr, v);
    }
    // layer 2: p = h@W2l^T (fp16), q = h@W2r^T (fp32)
    {
        dim3 grid(M_TILES, 2, 2);
        sage_mma_kernel<128, 256, 256, 0, 1><<<grid, 256, SMEM>>>(
            h16, h16 + 128, W2, nullptr, p, q, nullptr);
    }
    agg_fuse2_kernel<<<NTOT / 4, 128>>>(p, q, row_start, srcsort, b2_0, b2_1, out);

    cudaEventDestroy(evSplit);
    cudaEventDestroy(evV);
    cudaStreamDestroy(s2);
}

// round 11
// speedup vs baseline: 1.7661x; 1.0705x over previous
#include <cuda_runtime.h>
#include <cuda_fp16.h>
#include <math.h>
#include <stdint.h>

#define N_NODES 50000
#define NTOT    (2 * N_NODES)
#define NEDGE   800000
#define ETOT    (2 * NEDGE)
#define M_TILES ((N_NODES + 127) / 128)   // 391 per graph
#define SCAN_BLOCKS ((NTOT + 1023) / 1024)

// ================= device scratch =================
__device__ int   g_count[NTOT];
__device__ int   g_row_start[NTOT + 1];
__device__ int   g_cursor[NTOT];
__device__ int   g_srcsort[ETOT];
__device__ int   g_btot[SCAN_BLOCKS];
__device__ int   g_boff[SCAN_BLOCKS];
__device__ __half g_xh16[(size_t)NTOT * 128];
__device__ __half g_af16[(size_t)NTOT * 128];
__device__ __half g_h16[(size_t)NTOT * 256];
__device__ __half g_v[(size_t)NTOT * 256];
__device__ __half g_p[(size_t)NTOT * 128];
__device__ float  g_q[(size_t)NTOT * 128];
__device__ __half g_wf16[8 * 32768];

// ================= helpers =================
__device__ __forceinline__ uint32_t smem_u32(const void* p) {
    uint32_t a;
    asm("{ .reg .u64 t; cvta.to.shared.u64 t, %1; cvt.u32.u64 %0, t; }" : "=r"(a) : "l"(p));
    return a;
}
__device__ __forceinline__ void cp_async16(uint32_t dst, const void* src, bool valid) {
    if (valid) {
        asm volatile("cp.async.cg.shared.global [%0], [%1], 16;" :: "r"(dst), "l"(src));
    } else {
        asm volatile("cp.async.cg.shared.global [%0], [%1], 16, %2;"
                     :: "r"(dst), "l"(src), "r"(0u));
    }
}
#define CP_COMMIT()  asm volatile("cp.async.commit_group;" ::: "memory")
#define CP_WAIT1()   asm volatile("cp.async.wait_group 1;" ::: "memory")

__device__ __forceinline__ void ldsm4(uint32_t* r, uint32_t addr) {
    asm volatile("ldmatrix.sync.aligned.m8n8.x4.shared.b16 {%0,%1,%2,%3}, [%4];"
                 : "=r"(r[0]), "=r"(r[1]), "=r"(r[2]), "=r"(r[3]) : "r"(addr));
}
__device__ __forceinline__ void mma16816f16(float* d, const uint32_t* a, const uint32_t* b) {
    asm volatile(
        "mma.sync.aligned.m16n8k16.row.col.f32.f16.f16.f32 "
        "{%0,%1,%2,%3}, {%4,%5,%6,%7}, {%8,%9}, {%0,%1,%2,%3};"
        : "+f"(d[0]), "+f"(d[1]), "+f"(d[2]), "+f"(d[3])
        : "r"(a[0]), "r"(a[1]), "r"(a[2]), "r"(a[3]), "r"(b[0]), "r"(b[1]));
}

__device__ __forceinline__ float fast_tanh(float x) {
    float e = __expf(2.0f * x);
    return 1.0f - __fdividef(2.0f, e + 1.0f);
}

// ================= upfront fp32 -> fp16 conversion =================
struct SplitJobs {
    const float* src[10];
    __half* f16[10];
    int n4cum[11];
};

__global__ void split_all_kernel(SplitJobs J) {
    int f = blockIdx.x * blockDim.x + threadIdx.x;
    if (f >= J.n4cum[10]) return;
    int j = 0;
#pragma unroll
    for (int t = 0; t < 10; t++)
        if (f >= J.n4cum[t + 1]) j = t + 1;
    int local = f - J.n4cum[j];
    float4 v = *(const float4*)(J.src[j] + 4 * (size_t)local);
    __half2 a = __floats2half2_rn(v.x, v.y);
    __half2 b = __floats2half2_rn(v.z, v.w);
    uint2 pk;
    pk.x = *(uint32_t*)&a;
    pk.y = *(uint32_t*)&b;
    *(uint2*)(J.f16[j] + 4 * (size_t)local) = pk;
}

// ================= merged CSR build =================
__global__ void hist_kernel(const int* __restrict__ ei0, const int* __restrict__ ei1,
                            int* __restrict__ count) {
    int e = blockIdx.x * blockDim.x + threadIdx.x;
    if (e >= ETOT) return;
    int d;
    if (e < NEDGE) d = ei0[NEDGE + e];
    else           d = ei1[NEDGE + (e - NEDGE)] + N_NODES;
    atomicAdd(&count[d], 1);
}

__global__ void scan_part_kernel(int* __restrict__ counts, int* __restrict__ row_start,
                                 int* __restrict__ btot) {
    __shared__ int wsum[32];
    int tid = threadIdx.x, lane = tid & 31, w = tid >> 5;
    int i = blockIdx.x * 1024 + tid;
    int v = 0;
    if (i < NTOT) { v = counts[i]; counts[i] = 0; }
    int x = v;
#pragma unroll
    for (int off = 1; off < 32; off <<= 1) {
        int t = __shfl_up_sync(0xFFFFFFFFu, x, off);
        if (lane >= off) x += t;
    }
    if (lane == 31) wsum[w] = x;
    __syncthreads();
    if (w == 0) {
        int s = wsum[lane];
#pragma unroll
        for (int off = 1; off < 32; off <<= 1) {
            int t = __shfl_up_sync(0xFFFFFFFFu, s, off);
            if (lane >= off) s += t;
        }
        wsum[lane] = s;
    }
    __syncthreads();
    int excl = x - v + (w ? wsum[w - 1] : 0);
    if (i < NTOT) row_start[i] = excl;
    if (tid == 0) btot[blockIdx.x] = wsum[31];
}

__global__ void scan_tops_kernel(const int* __restrict__ btot, int* __restrict__ boff) {
    __shared__ int sh[128];
    int tid = threadIdx.x;
    int v = (tid < SCAN_BLOCKS) ? btot[tid] : 0;
    sh[tid] = v;
    __syncthreads();
    for (int off = 1; off < 128; off <<= 1) {
        int t = (tid >= off) ? sh[tid - off] : 0;
        __syncthreads();
        sh[tid] += t;
        __syncthreads();
    }
    if (tid < SCAN_BLOCKS) boff[tid] = sh[tid] - v;
}

__global__ void scan_add_kernel(const int* __restrict__ boff, int* __restrict__ row_start,
                                int* __restrict__ cursor) {
    int i = blockIdx.x * 1024 + threadIdx.x;
    if (i < NTOT) {
        int rs = row_start[i] + boff[blockIdx.x];
        row_start[i] = rs;
        cursor[i] = rs;
    }
    if (i == NTOT - 1) row_start[NTOT] = ETOT;
}

__global__ void scatter_kernel(const int* __restrict__ ei0, const int* __restrict__ ei1,
                               int* __restrict__ cursor, int* __restrict__ srcsort) {
    int e = blockIdx.x * blockDim.x + threadIdx.x;
    if (e >= ETOT) return;
    int s, d;
    if (e < NEDGE) {
        s = ei0[e];
        d = ei0[NEDGE + e];
    } else {
        int e1 = e - NEDGE;
        s = ei1[e1] + N_NODES;
        d = ei1[NEDGE + e1] + N_NODES;
    }
    int p = atomicAdd(&cursor[d], 1);
    srcsort[p] = s;
}

// ================= layer-1 mean aggregation (16B loads, 8 nodes/block) ============
__global__ void aggregate1_kernel(const __half* __restrict__ xh,
                                  const int* __restrict__ row_start,
                                  const int* __restrict__ srcsort,
                                  __half* __restrict__ oa, int node_base) {
    int local = threadIdx.x >> 4;              // 8 nodes per 128-thread block
    int t8 = (threadIdx.x & 15) * 8;           // 8 dims per thread
    int node = node_base + blockIdx.x * 8 + local;
    int s0 = row_start[node];
    int s1 = row_start[node + 1];
    float a[8];
#pragma unroll
    for (int i = 0; i < 8; i++) a[i] = 0.f;
    int e = s0;
    for (; e + 2 <= s1; e += 2) {
        uint4 vA = *(const uint4*)(xh + (size_t)srcsort[e] * 128 + t8);
        uint4 vB = *(const uint4*)(xh + (size_t)srcsort[e + 1] * 128 + t8);
        const uint32_t* wA = &vA.x;
        const uint32_t* wB = &vB.x;
#pragma unroll
        for (int i = 0; i < 4; i++) {
            float2 fA = __half22float2(*(__half2*)&wA[i]);
            float2 fB = __half22float2(*(__half2*)&wB[i]);
            a[2 * i] += fA.x + fB.x;
            a[2 * i + 1] += fA.y + fB.y;
        }
    }
    if (e < s1) {
        uint4 v = *(const uint4*)(xh + (size_t)srcsort[e] * 128 + t8);
        const uint32_t* w = &v.x;
#pragma unroll
        for (int i = 0; i < 4; i++) {
            float2 f = __half22float2(*(__half2*)&w[i]);
            a[2 * i] += f.x;
            a[2 * i + 1] += f.y;
        }
    }
    float inv = 1.0f / (float)max(s1 - s0, 1);
    uint4 pk;
    uint32_t* pw = &pk.x;
#pragma unroll
    for (int i = 0; i < 4; i++) {
        __half2 h = __floats2half2_rn(a[2 * i] * inv, a[2 * i + 1] * inv);
        pw[i] = *(uint32_t*)&h;
    }
    *(uint4*)(oa + (size_t)node * 128 + t8) = pk;
}

// ================= layer-2 fused aggregation + epilogue (16B loads) ===============
__global__ void agg_fuse2_kernel(const __half* __restrict__ p,
                                 const float* __restrict__ q,
                                 const int* __restrict__ row_start,
                                 const int* __restrict__ srcsort,
                                 const float* __restrict__ bias,
                                 float* __restrict__ out, int node_base) {
    int local = threadIdx.x >> 4;
    int t8 = (threadIdx.x & 15) * 8;
    int node = node_base + blockIdx.x * 8 + local;
    int s0 = row_start[node];
    int s1 = row_start[node + 1];
    float a[8];
#pragma unroll
    for (int i = 0; i < 8; i++) a[i] = 0.f;
    int e = s0;
    for (; e + 2 <= s1; e += 2) {
        uint4 vA = *(const uint4*)(p + (size_t)srcsort[e] * 128 + t8);
        uint4 vB = *(const uint4*)(p + (size_t)srcsort[e + 1] * 128 + t8);
        const uint32_t* wA = &vA.x;
        const uint32_t* wB = &vB.x;
#pragma unroll
        for (int i = 0; i < 4; i++) {
            float2 fA = __half22float2(*(__half2*)&wA[i]);
            float2 fB = __half22float2(*(__half2*)&wB[i]);
            a[2 * i] += fA.x + fB.x;
            a[2 * i + 1] += fA.y + fB.y;
        }
    }
    if (e < s1) {
        uint4 v = *(const uint4*)(p + (size_t)srcsort[e] * 128 + t8);
        const uint32_t* w = &v.x;
#pragma unroll
        for (int i = 0; i < 4; i++) {
            float2 f = __half22float2(*(__half2*)&w[i]);
            a[2 * i] += f.x;
            a[2 * i + 1] += f.y;
        }
    }
    float inv = 1.0f / (float)max(s1 - s0, 1);
    float4 q0 = *(const float4*)(q + (size_t)node * 128 + t8);
    float4 q1 = *(const float4*)(q + (size_t)node * 128 + t8 + 4);
    float4 b0 = *(const float4*)(bias + t8);
    float4 b1 = *(const float4*)(bias + t8 + 4);
    float4 o0, o1;
    o0.x = fast_tanh(a[0] * inv + q0.x + b0.x);
    o0.y = fast_tanh(a[1] * inv + q0.y + b0.y);
    o0.z = fast_tanh(a[2] * inv + q0.z + b0.z);
    o0.w = fast_tanh(a[3] * inv + q0.w + b0.w);
    o1.x = fast_tanh(a[4] * inv + q1.x + b1.x);
    o1.y = fast_tanh(a[5] * inv + q1.y + b1.y);
    o1.z = fast_tanh(a[6] * inv + q1.z + b1.z);
    o1.w = fast_tanh(a[7] * inv + q1.w + b1.w);
    *(float4*)(out + (size_t)node * 128 + t8) = o0;
    *(float4*)(out + (size_t)node * 128 + t8 + 4) = o1;
}

// ================= fp16 mma.sync GEMM =================
struct GemmW {
    const __half* b0[2][2];   // [y][g]
    const __half* b1[2][2];
    const float* bias[2];
};

// MODE 1: layer2 p/q ; MODE 2: v = x@W1r^T ; MODE 3: h = tanh(acc + v + bias)
template <int KHALF, int ASTRIDE, int BSTRIDE, int BOFF, int MODE>
__global__ void __launch_bounds__(256, 2)
sage_mma_kernel(const __half* __restrict__ a0, const __half* __restrict__ a1,
                GemmW W,
                __half* __restrict__ oh, __half* __restrict__ op,
                float* __restrict__ oq, const __half* __restrict__ vin, int gbase) {
    constexpr int NC = 2 * KHALF / 32;
    constexpr int MATB = 10240;
    constexpr int STAGE = 2 * MATB;
    constexpr int MT = 4;

    extern __shared__ char smem[];
    uint32_t sb = smem_u32(smem);

    int tid = threadIdx.x;
    int wid = tid >> 5;
    int lane = tid & 31;
    int wm = wid & 1;
    int wn = wid >> 1;
    int y = blockIdx.y;
    int g = gbase + blockIdx.z;
    int m0 = g * N_NODES + blockIdx.x * 128;
    int Mlim = (g + 1) * N_NODES;
    int n0 = y * 128;
    int bn0 = y * BOFF;

    const __half* B0 = W.b0[y][g];
    const __half* B1 = W.b1[y][g];

    auto issue = [&](int c) {
        int half = (c * 32 >= KHALF) ? 1 : 0;
        int kh0 = c * 32 - half * KHALF;
        const __half* A = half ? a1 : a0;
        const __half* B = half ? B1 : B0;
        uint32_t st = sb + (c & 1) * STAGE;
#pragma unroll
        for (int i = 0; i < 4; i++) {
            int idx = i * 256 + tid;
            int r = idx >> 2;
            int ch = idx & 3;
            if (r < 128) {
                int m = m0 + r;
                bool valid = (m < Mlim);
                const __half* pp = A + (size_t)(valid ? m : 0) * ASTRIDE + kh0 + ch * 8;
                cp_async16(st + r * 80 + ch * 16, pp, valid);
            } else {
                int rl = r - 128;
                cp_async16(st + MATB + rl * 80 + ch * 16,
                           B + (size_t)(bn0 + rl) * BSTRIDE + kh0 + ch * 8, true);
            }
        }
    };

    float acc[MT][4][4];
#pragma unroll
    for (int i = 0; i < MT; i++)
#pragma unroll
        for (int j = 0; j < 4; j++)
#pragma unroll
            for (int k = 0; k < 4; k++) acc[i][j][k] = 0.f;

    issue(0); CP_COMMIT();
    issue(1); CP_COMMIT();

    uint32_t a_row = (uint32_t)(wm * 64 + (lane & 15)) * 80 + (lane >> 4) * 16;
    uint32_t b_row = (uint32_t)(wn * 32 + (lane & 7) + ((lane >> 4) << 3)) * 80 +
                     ((lane >> 3) & 1) * 16;

    for (int c = 0; c < NC; c++) {
        CP_WAIT1();
        __syncthreads();
        uint32_t st = sb + (c & 1) * STAGE;
#pragma unroll
        for (int ks = 0; ks < 2; ks++) {
            uint32_t ko = ks * 32;
            uint32_t Af[MT][4], Bf[2][4];
#pragma unroll
            for (int mt = 0; mt < MT; mt++)
                ldsm4(Af[mt], st + a_row + (uint32_t)mt * (16 * 80) + ko);
#pragma unroll
            for (int nt2 = 0; nt2 < 2; nt2++)
                ldsm4(Bf[nt2], st + MATB + b_row + (uint32_t)nt2 * (16 * 80) + ko);
#pragma unroll
            for (int mt = 0; mt < MT; mt++) {
#pragma unroll
                for (int nt = 0; nt < 4; nt++) {
                    mma16816f16(acc[mt][nt], Af[mt], &Bf[nt >> 1][(nt & 1) * 2]);
                }
            }
        }
        __syncthreads();
        if (c + 2 < NC) issue(c + 2);
        CP_COMMIT();
    }

    int gq = lane >> 2, t4 = lane & 3;
    const float* bias = (MODE == 3) ? W.bias[g] : nullptr;
#pragma unroll
    for (int mt = 0; mt < MT; mt++) {
#pragma unroll
        for (int nt = 0; nt < 4; nt++) {
            int col = wn * 32 + nt * 8 + 2 * t4;
            float b0 = (MODE == 3) ? bias[n0 + col] : 0.f;
            float b1 = (MODE == 3) ? bias[n0 + col + 1] : 0.f;
#pragma unroll
            for (int hrow = 0; hrow < 2; hrow++) {
                int row = m0 + wm * 64 + mt * 16 + gq + hrow * 8;
                if (row < Mlim) {
                    float v0 = acc[mt][nt][2 * hrow + 0];
                    float v1 = acc[mt][nt][2 * hrow + 1];
                    if (MODE == 1) {
                        size_t ob = (size_t)row * 128 + col;
                        if (y == 0) {
                            *(__half2*)(op + ob) = __floats2half2_rn(v0, v1);
                        } else {
                            float2 o; o.x = v0; o.y = v1;
                            *(float2*)(oq + ob) = o;
                        }
                    } else if (MODE == 2) {
                        size_t ob = (size_t)row * 256 + n0 + col;
                        *(__half2*)(op + ob) = __floats2half2_rn(v0, v1);
                    } else {
                        size_t ob = (size_t)row * 256 + n0 + col;
                        float2 vv = __half22float2(*(const __half2*)(vin + ob));
                        v0 = fast_tanh(v0 + vv.x + b0);
                        v1 = fast_tanh(v1 + vv.y + b1);
                        *(__half2*)(oh + ob) = __floats2half2_rn(v0, v1);
                    }
                }
            }
        }
    }
}

// ================= host =================
extern "C" void kernel_launch(void* const* d_in, const int* in_sizes, int n_in,
                              void* d_out, int out_size) {
    (void)in_sizes; (void)n_in; (void)out_size;

    const float* x0  = (const float*)d_in[0];
    const float* x1  = (const float*)d_in[1];
    const int*   ei0 = (const int*)d_in[2];
    const int*   ei1 = (const int*)d_in[3];
    const float* W1l_0 = (const float*)d_in[4];
    const float* b1_0  = (const float*)d_in[5];
    const float* W1r_0 = (const float*)d_in[6];
    const float* W2l_0 = (const float*)d_in[7];
    const float* b2_0  = (const float*)d_in[8];
    const float* W2r_0 = (const float*)d_in[9];
    const float* W1l_1 = (const float*)d_in[10];
    const float* b1_1  = (const float*)d_in[11];
    const float* W1r_1 = (const float*)d_in[12];
    const float* W2l_1 = (const float*)d_in[13];
    const float* b2_1  = (const float*)d_in[14];
    const float* W2r_1 = (const float*)d_in[15];
    float* out = (float*)d_out;

    constexpr int SMEM = 2 * 2 * 10240;  // 40960

    int *count, *row_start, *cursor, *srcsort, *btot, *boff;
    __half *xh16, *af16, *h16, *v, *p, *wf16;
    float *q;
    cudaGetSymbolAddress((void**)&count, g_count);
    cudaGetSymbolAddress((void**)&row_start, g_row_start);
    cudaGetSymbolAddress((void**)&cursor, g_cursor);
    cudaGetSymbolAddress((void**)&srcsort, g_srcsort);
    cudaGetSymbolAddress((void**)&btot, g_btot);
    cudaGetSymbolAddress((void**)&boff, g_boff);
    cudaGetSymbolAddress((void**)&xh16, g_xh16);
    cudaGetSymbolAddress((void**)&af16, g_af16);
    cudaGetSymbolAddress((void**)&h16, g_h16);
    cudaGetSymbolAddress((void**)&v, g_v);
    cudaGetSymbolAddress((void**)&p, g_p);
    cudaGetSymbolAddress((void**)&q, g_q);
    cudaGetSymbolAddress((void**)&wf16, g_wf16);

    SplitJobs J;
    const float* srcs[10] = {x0, x1, W1l_0, W1r_0, W2l_0, W2r_0, W1l_1, W1r_1, W2l_1, W2r_1};
    int counts[10] = {N_NODES * 128, N_NODES * 128,
                      32768, 32768, 32768, 32768, 32768, 32768, 32768, 32768};
    int cum = 0;
    for (int j = 0; j < 10; j++) {
        J.src[j] = srcs[j];
        if (j == 0)      J.f16[j] = xh16;
        else if (j == 1) J.f16[j] = xh16 + (size_t)N_NODES * 128;
        else             J.f16[j] = wf16 + (j - 2) * 32768;
        J.n4cum[j] = cum;
        cum += counts[j] / 4;
    }
    J.n4cum[10] = cum;

    GemmW Wv, Wu, W2;
    for (int g = 0; g < 2; g++) {
        for (int y = 0; y < 2; y++) {
            Wv.b0[y][g] = wf16 + (4 * g + 1) * 32768;
            Wv.b1[y][g] = wf16 + (4 * g + 1) * 32768 + 64;
            Wu.b0[y][g] = wf16 + (4 * g + 0) * 32768;
            Wu.b1[y][g] = wf16 + (4 * g + 0) * 32768 + 64;
        }
        W2.b0[0][g] = wf16 + (4 * g + 2) * 32768;
        W2.b1[0][g] = wf16 + (4 * g + 2) * 32768 + 128;
        W2.b0[1][g] = wf16 + (4 * g + 3) * 32768;
        W2.b1[1][g] = wf16 + (4 * g + 3) * 32768 + 128;
    }
    Wu.bias[0] = b1_0; Wu.bias[1] = b1_1;
    Wv.bias[0] = nullptr; Wv.bias[1] = nullptr;
    W2.bias[0] = nullptr; W2.bias[1] = nullptr;

    cudaStream_t s2;
    cudaStreamCreateWithFlags(&s2, cudaStreamNonBlocking);
    cudaEvent_t evSplit, evV, evA0, evD0;
    cudaEventCreateWithFlags(&evSplit, cudaEventDisableTiming);
    cudaEventCreateWithFlags(&evV, cudaEventDisableTiming);
    cudaEventCreateWithFlags(&evA0, cudaEventDisableTiming);
    cudaEventCreateWithFlags(&evD0, cudaEventDisableTiming);

    // main: split
    split_all_kernel<<<(cum + 255) / 256, 256>>>(J);
    cudaEventRecord(evSplit, 0);

    // s2: v = x @ W1r^T (both graphs, tensor) overlapping CSR+agg1 (memory)
    cudaStreamWaitEvent(s2, evSplit, 0);
    {
        dim3 grid(M_TILES, 2, 2);
        sage_mma_kernel<64, 128, 128, 128, 2><<<grid, 256, SMEM, s2>>>(
            xh16, xh16 + 64, Wv, nullptr, v, nullptr, nullptr, 0);
    }
    cudaEventRecord(evV, s2);

    // main: CSR chain
    hist_kernel<<<(ETOT + 255) / 256, 256>>>(ei0, ei1, count);
    scan_part_kernel<<<SCAN_BLOCKS, 1024>>>(count, row_start, btot);
    scan_tops_kernel<<<1, 128>>>(btot, boff);
    scan_add_kernel<<<SCAN_BLOCKS, 1024>>>(boff, row_start, cursor);
    scatter_kernel<<<(ETOT + 255) / 256, 256>>>(ei0, ei1, cursor, srcsort);

    // main: agg1(g0), then agg1(g1)
    aggregate1_kernel<<<N_NODES / 8, 128>>>(xh16, row_start, srcsort, af16, 0);
    cudaEventRecord(evA0, 0);
    aggregate1_kernel<<<N_NODES / 8, 128>>>(xh16, row_start, srcsort, af16, N_NODES);

    // s2 chain for graph 0: u(g0) -> gemm2(g0) -> aggf2(g0)
    cudaStreamWaitEvent(s2, evA0, 0);
    {
        dim3 grid(M_TILES, 2, 1);
        sage_mma_kernel<64, 128, 128, 128, 3><<<grid, 256, SMEM, s2>>>(
            af16, af16 + 64, Wu, h16, nullptr, nullptr, v, 0);
        sage_mma_kernel<128, 256, 256, 0, 1><<<grid, 256, SMEM, s2>>>(
            h16, h16 + 128, W2, nullptr, p, q, nullptr, 0);
    }
    agg_fuse2_kernel<<<N_NODES / 8, 128, 0, s2>>>(p, q, row_start, srcsort, b2_0, out, 0);
    cudaEventRecord(evD0, s2);

    // main chain for graph 1 (needs v from s2)
    cudaStreamWaitEvent(0, evV, 0);
    {
        dim3 grid(M_TILES, 2, 1);
        sage_mma_kernel<64, 128, 128, 128, 3><<<grid, 256, SMEM>>>(
            af16, af16 + 64, Wu, h16, nullptr, nullptr, v, 1);
        sage_mma_kernel<128, 256, 256, 0, 1><<<grid, 256, SMEM>>>(
            h16, h16 + 128, W2, nullptr, p, q, nullptr, 1);
    }
    agg_fuse2_kernel<<<N_NODES / 8, 128>>>(p, q, row_start, srcsort, b2_1, out, N_NODES);

    // join
    cudaStreamWaitEvent(0, evD0, 0);

    cudaEventDestroy(evSplit);
    cudaEventDestroy(evV);
    cudaEventDestroy(evA0);
    cudaEventDestroy(evD0);
    cudaStreamDestroy(s2);
}

// round 12
// speedup vs baseline: 1.7783x; 1.0069x over previous
#include <cuda_runtime.h>
#include <cuda_fp16.h>
#include <math.h>
#include <stdint.h>

#define N_NODES 50000
#define NTOT    (2 * N_NODES)
#define NEDGE   800000
#define ETOT    (2 * NEDGE)
#define M_TILES ((N_NODES + 127) / 128)   // 391 per graph
#define SCAN_BLOCKS ((NTOT + 1023) / 1024)

// ================= device scratch =================
__device__ int   g_count[NTOT];
__device__ int   g_row_start[NTOT + 1];
__device__ int   g_cursor[NTOT];
__device__ int   g_srcsort[ETOT];
__device__ int   g_btot[SCAN_BLOCKS];
__device__ int   g_boff[SCAN_BLOCKS];
__device__ __half g_xh16[(size_t)NTOT * 128];
__device__ __half g_af16[(size_t)NTOT * 128];
__device__ __half g_h16[(size_t)NTOT * 256];
__device__ __half g_v[(size_t)NTOT * 256];
__device__ __half g_p[(size_t)NTOT * 128];
__device__ __half g_q16[(size_t)NTOT * 128];
__device__ __half g_wf16[8 * 32768];

// ================= helpers =================
__device__ __forceinline__ uint32_t smem_u32(const void* p) {
    uint32_t a;
    asm("{ .reg .u64 t; cvta.to.shared.u64 t, %1; cvt.u32.u64 %0, t; }" : "=r"(a) : "l"(p));
    return a;
}
__device__ __forceinline__ void cp_async16(uint32_t dst, const void* src, bool valid) {
    if (valid) {
        asm volatile("cp.async.cg.shared.global [%0], [%1], 16;" :: "r"(dst), "l"(src));
    } else {
        asm volatile("cp.async.cg.shared.global [%0], [%1], 16, %2;"
                     :: "r"(dst), "l"(src), "r"(0u));
    }
}
#define CP_COMMIT()  asm volatile("cp.async.commit_group;" ::: "memory")
#define CP_WAIT1()   asm volatile("cp.async.wait_group 1;" ::: "memory")

__device__ __forceinline__ void ldsm4(uint32_t* r, uint32_t addr) {
    asm volatile("ldmatrix.sync.aligned.m8n8.x4.shared.b16 {%0,%1,%2,%3}, [%4];"
                 : "=r"(r[0]), "=r"(r[1]), "=r"(r[2]), "=r"(r[3]) : "r"(addr));
}
__device__ __forceinline__ void mma16816f16(float* d, const uint32_t* a, const uint32_t* b) {
    asm volatile(
        "mma.sync.aligned.m16n8k16.row.col.f32.f16.f16.f32 "
        "{%0,%1,%2,%3}, {%4,%5,%6,%7}, {%8,%9}, {%0,%1,%2,%3};"
        : "+f"(d[0]), "+f"(d[1]), "+f"(d[2]), "+f"(d[3])
        : "r"(a[0]), "r"(a[1]), "r"(a[2]), "r"(a[3]), "r"(b[0]), "r"(b[1]));
}

__device__ __forceinline__ float fast_tanh(float x) {
    float e = __expf(2.0f * x);
    return 1.0f - __fdividef(2.0f, e + 1.0f);
}

// ================= upfront fp32 -> fp16 conversion =================
struct SplitJobs {
    const float* src[10];
    __half* f16[10];
    int n4cum[11];
};

__global__ void split_all_kernel(SplitJobs J) {
    int f = blockIdx.x * blockDim.x + threadIdx.x;
    if (f >= J.n4cum[10]) return;
    int j = 0;
#pragma unroll
    for (int t = 0; t < 10; t++)
        if (f >= J.n4cum[t + 1]) j = t + 1;
    int local = f - J.n4cum[j];
    float4 v = *(const float4*)(J.src[j] + 4 * (size_t)local);
    __half2 a = __floats2half2_rn(v.x, v.y);
    __half2 b = __floats2half2_rn(v.z, v.w);
    uint2 pk;
    pk.x = *(uint32_t*)&a;
    pk.y = *(uint32_t*)&b;
    *(uint2*)(J.f16[j] + 4 * (size_t)local) = pk;
}

// ================= merged CSR build =================
// 2 edges per thread, vectorized dst reads
__global__ void hist_kernel(const int* __restrict__ ei0, const int* __restrict__ ei1,
                            int* __restrict__ count) {
    int t = blockIdx.x * blockDim.x + threadIdx.x;
    int e = t * 2;
    if (e >= ETOT) return;
    if (e < NEDGE) {
        int2 d = *(const int2*)(ei0 + NEDGE + e);
        atomicAdd(&count[d.x], 1);
        atomicAdd(&count[d.y], 1);
    } else {
        int2 d = *(const int2*)(ei1 + NEDGE + (e - NEDGE));
        atomicAdd(&count[d.x + N_NODES], 1);
        atomicAdd(&count[d.y + N_NODES], 1);
    }
}

__global__ void scan_part_kernel(int* __restrict__ counts, int* __restrict__ row_start,
                                 int* __restrict__ btot) {
    __shared__ int wsum[32];
    int tid = threadIdx.x, lane = tid & 31, w = tid >> 5;
    int i = blockIdx.x * 1024 + tid;
    int v = 0;
    if (i < NTOT) { v = counts[i]; counts[i] = 0; }
    int x = v;
#pragma unroll
    for (int off = 1; off < 32; off <<= 1) {
        int t = __shfl_up_sync(0xFFFFFFFFu, x, off);
        if (lane >= off) x += t;
    }
    if (lane == 31) wsum[w] = x;
    __syncthreads();
    if (w == 0) {
        int s = wsum[lane];
#pragma unroll
        for (int off = 1; off < 32; off <<= 1) {
            int t = __shfl_up_sync(0xFFFFFFFFu, s, off);
            if (lane >= off) s += t;
        }
        wsum[lane] = s;
    }
    __syncthreads();
    int excl = x - v + (w ? wsum[w - 1] : 0);
    if (i < NTOT) row_start[i] = excl;
    if (tid == 0) btot[blockIdx.x] = wsum[31];
}

__global__ void scan_tops_kernel(const int* __restrict__ btot, int* __restrict__ boff) {
    __shared__ int sh[128];
    int tid = threadIdx.x;
    int v = (tid < SCAN_BLOCKS) ? btot[tid] : 0;
    sh[tid] = v;
    __syncthreads();
    for (int off = 1; off < 128; off <<= 1) {
        int t = (tid >= off) ? sh[tid - off] : 0;
        __syncthreads();
        sh[tid] += t;
        __syncthreads();
    }
    if (tid < SCAN_BLOCKS) boff[tid] = sh[tid] - v;
}

__global__ void scan_add_kernel(const int* __restrict__ boff, int* __restrict__ row_start,
                                int* __restrict__ cursor) {
    int i = blockIdx.x * 1024 + threadIdx.x;
    if (i < NTOT) {
        int rs = row_start[i] + boff[blockIdx.x];
        row_start[i] = rs;
        cursor[i] = rs;
    }
    if (i == NTOT - 1) row_start[NTOT] = ETOT;
}

__global__ void scatter_kernel(const int* __restrict__ ei0, const int* __restrict__ ei1,
                               int* __restrict__ cursor, int* __restrict__ srcsort) {
    int e = blockIdx.x * blockDim.x + threadIdx.x;
    if (e >= ETOT) return;
    int s, d;
    if (e < NEDGE) {
        s = ei0[e];
        d = ei0[NEDGE + e];
    } else {
        int e1 = e - NEDGE;
        s = ei1[e1] + N_NODES;
        d = ei1[NEDGE + e1] + N_NODES;
    }
    int p = atomicAdd(&cursor[d], 1);
    srcsort[p] = s;
}

// ================= layer-1 mean aggregation (16B loads, 8 nodes/block) ============
__global__ void aggregate1_kernel(const __half* __restrict__ xh,
                                  const int* __restrict__ row_start,
                                  const int* __restrict__ srcsort,
                                  __half* __restrict__ oa, int node_base) {
    int local = threadIdx.x >> 4;
    int t8 = (threadIdx.x & 15) * 8;
    int node = node_base + blockIdx.x * 8 + local;
    int s0 = row_start[node];
    int s1 = row_start[node + 1];
    float a[8];
#pragma unroll
    for (int i = 0; i < 8; i++) a[i] = 0.f;
    int e = s0;
    for (; e + 2 <= s1; e += 2) {
        uint4 vA = *(const uint4*)(xh + (size_t)srcsort[e] * 128 + t8);
        uint4 vB = *(const uint4*)(xh + (size_t)srcsort[e + 1] * 128 + t8);
        const uint32_t* wA = &vA.x;
        const uint32_t* wB = &vB.x;
#pragma unroll
        for (int i = 0; i < 4; i++) {
            float2 fA = __half22float2(*(__half2*)&wA[i]);
            float2 fB = __half22float2(*(__half2*)&wB[i]);
            a[2 * i] += fA.x + fB.x;
            a[2 * i + 1] += fA.y + fB.y;
        }
    }
    if (e < s1) {
        uint4 v = *(const uint4*)(xh + (size_t)srcsort[e] * 128 + t8);
        const uint32_t* w = &v.x;
#pragma unroll
        for (int i = 0; i < 4; i++) {
            float2 f = __half22float2(*(__half2*)&w[i]);
            a[2 * i] += f.x;
            a[2 * i + 1] += f.y;
        }
    }
    float inv = 1.0f / (float)max(s1 - s0, 1);
    uint4 pk;
    uint32_t* pw = &pk.x;
#pragma unroll
    for (int i = 0; i < 4; i++) {
        __half2 h = __floats2half2_rn(a[2 * i] * inv, a[2 * i + 1] * inv);
        pw[i] = *(uint32_t*)&h;
    }
    *(uint4*)(oa + (size_t)node * 128 + t8) = pk;
}

// ================= layer-2 fused aggregation + epilogue (fp16 p and q) ============
__global__ void agg_fuse2_kernel(const __half* __restrict__ p,
                                 const __half* __restrict__ q,
                                 const int* __restrict__ row_start,
                                 const int* __restrict__ srcsort,
                                 const float* __restrict__ bias,
                                 float* __restrict__ out, int node_base) {
    int local = threadIdx.x >> 4;
    int t8 = (threadIdx.x & 15) * 8;
    int node = node_base + blockIdx.x * 8 + local;
    int s0 = row_start[node];
    int s1 = row_start[node + 1];
    float a[8];
#pragma unroll
    for (int i = 0; i < 8; i++) a[i] = 0.f;
    int e = s0;
    for (; e + 2 <= s1; e += 2) {
        uint4 vA = *(const uint4*)(p + (size_t)srcsort[e] * 128 + t8);
        uint4 vB = *(const uint4*)(p + (size_t)srcsort[e + 1] * 128 + t8);
        const uint32_t* wA = &vA.x;
        const uint32_t* wB = &vB.x;
#pragma unroll
        for (int i = 0; i < 4; i++) {
            float2 fA = __half22float2(*(__half2*)&wA[i]);
            float2 fB = __half22float2(*(__half2*)&wB[i]);
            a[2 * i] += fA.x + fB.x;
            a[2 * i + 1] += fA.y + fB.y;
        }
    }
    if (e < s1) {
        uint4 v = *(const uint4*)(p + (size_t)srcsort[e] * 128 + t8);
        const uint32_t* w = &v.x;
#pragma unroll
        for (int i = 0; i < 4; i++) {
            float2 f = __half22float2(*(__half2*)&w[i]);
            a[2 * i] += f.x;
            a[2 * i + 1] += f.y;
        }
    }
    float inv = 1.0f / (float)max(s1 - s0, 1);
    uint4 qv = *(const uint4*)(q + (size_t)node * 128 + t8);
    const uint32_t* qw = &qv.x;
    float4 b0 = *(const float4*)(bias + t8);
    float4 b1 = *(const float4*)(bias + t8 + 4);
    float qq[8];
#pragma unroll
    for (int i = 0; i < 4; i++) {
        float2 f = __half22float2(*(__half2*)&qw[i]);
        qq[2 * i] = f.x;
        qq[2 * i + 1] = f.y;
    }
    float4 o0, o1;
    o0.x = fast_tanh(a[0] * inv + qq[0] + b0.x);
    o0.y = fast_tanh(a[1] * inv + qq[1] + b0.y);
    o0.z = fast_tanh(a[2] * inv + qq[2] + b0.z);
    o0.w = fast_tanh(a[3] * inv + qq[3] + b0.w);
    o1.x = fast_tanh(a[4] * inv + qq[4] + b1.x);
    o1.y = fast_tanh(a[5] * inv + qq[5] + b1.y);
    o1.z = fast_tanh(a[6] * inv + qq[6] + b1.z);
    o1.w = fast_tanh(a[7] * inv + qq[7] + b1.w);
    *(float4*)(out + (size_t)node * 128 + t8) = o0;
    *(float4*)(out + (size_t)node * 128 + t8 + 4) = o1;
}

// ================= fp16 mma.sync GEMM =================
struct GemmW {
    const __half* b0[2][2];
    const __half* b1[2][2];
    const float* bias[2];
};

// MODE 1: layer2 p/q (both fp16) ; MODE 2: v = x@W1r^T ; MODE 3: h = tanh(acc+v+bias)
template <int KHALF, int ASTRIDE, int BSTRIDE, int BOFF, int MODE>
__global__ void __launch_bounds__(256, 2)
sage_mma_kernel(const __half* __restrict__ a0, const __half* __restrict__ a1,
                GemmW W,
                __half* __restrict__ oh, __half* __restrict__ op,
                __half* __restrict__ oq, const __half* __restrict__ vin, int gbase) {
    constexpr int NC = 2 * KHALF / 32;
    constexpr int MATB = 10240;
    constexpr int STAGE = 2 * MATB;
    constexpr int MT = 4;

    extern __shared__ char smem[];
    uint32_t sb = smem_u32(smem);

    int tid = threadIdx.x;
    int wid = tid >> 5;
    int lane = tid & 31;
    int wm = wid & 1;
    int wn = wid >> 1;
    int y = blockIdx.y;
    int g = gbase + blockIdx.z;
    int m0 = g * N_NODES + blockIdx.x * 128;
    int Mlim = (g + 1) * N_NODES;
    int n0 = y * 128;
    int bn0 = y * BOFF;

    const __half* B0 = W.b0[y][g];
    const __half* B1 = W.b1[y][g];

    auto issue = [&](int c) {
        int half = (c * 32 >= KHALF) ? 1 : 0;
        int kh0 = c * 32 - half * KHALF;
        const __half* A = half ? a1 : a0;
        const __half* B = half ? B1 : B0;
        uint32_t st = sb + (c & 1) * STAGE;
#pragma unroll
        for (int i = 0; i < 4; i++) {
            int idx = i * 256 + tid;
            int r = idx >> 2;
            int ch = idx & 3;
            if (r < 128) {
                int m = m0 + r;
                bool valid = (m < Mlim);
                const __half* pp = A + (size_t)(valid ? m : 0) * ASTRIDE + kh0 + ch * 8;
                cp_async16(st + r * 80 + ch * 16, pp, valid);
            } else {
                int rl = r - 128;
                cp_async16(st + MATB + rl * 80 + ch * 16,
                           B + (size_t)(bn0 + rl) * BSTRIDE + kh0 + ch * 8, true);
            }
        }
    };

    float acc[MT][4][4];
#pragma unroll
    for (int i = 0; i < MT; i++)
#pragma unroll
        for (int j = 0; j < 4; j++)
#pragma unroll
            for (int k = 0; k < 4; k++) acc[i][j][k] = 0.f;

    issue(0); CP_COMMIT();
    issue(1); CP_COMMIT();

    uint32_t a_row = (uint32_t)(wm * 64 + (lane & 15)) * 80 + (lane >> 4) * 16;
    uint32_t b_row = (uint32_t)(wn * 32 + (lane & 7) + ((lane >> 4) << 3)) * 80 +
                     ((lane >> 3) & 1) * 16;

    for (int c = 0; c < NC; c++) {
        CP_WAIT1();
        __syncthreads();
        uint32_t st = sb + (c & 1) * STAGE;
#pragma unroll
        for (int ks = 0; ks < 2; ks++) {
            uint32_t ko = ks * 32;
            uint32_t Af[MT][4], Bf[2][4];
#pragma unroll
            for (int mt = 0; mt < MT; mt++)
                ldsm4(Af[mt], st + a_row + (uint32_t)mt * (16 * 80) + ko);
#pragma unroll
            for (int nt2 = 0; nt2 < 2; nt2++)
                ldsm4(Bf[nt2], st + MATB + b_row + (uint32_t)nt2 * (16 * 80) + ko);
#pragma unroll
            for (int mt = 0; mt < MT; mt++) {
#pragma unroll
                for (int nt = 0; nt < 4; nt++) {
                    mma16816f16(acc[mt][nt], Af[mt], &Bf[nt >> 1][(nt & 1) * 2]);
                }
            }
        }
        __syncthreads();
        if (c + 2 < NC) issue(c + 2);
        CP_COMMIT();
    }

    int gq = lane >> 2, t4 = lane & 3;
    const float* bias = (MODE == 3) ? W.bias[g] : nullptr;
#pragma unroll
    for (int mt = 0; mt < MT; mt++) {
#pragma unroll
        for (int nt = 0; nt < 4; nt++) {
            int col = wn * 32 + nt * 8 + 2 * t4;
            float b0 = (MODE == 3) ? bias[n0 + col] : 0.f;
            float b1 = (MODE == 3) ? bias[n0 + col + 1] : 0.f;
#pragma unroll
            for (int hrow = 0; hrow < 2; hrow++) {
                int row = m0 + wm * 64 + mt * 16 + gq + hrow * 8;
                if (row < Mlim) {
                    float v0 = acc[mt][nt][2 * hrow + 0];
                    float v1 = acc[mt][nt][2 * hrow + 1];
                    if (MODE == 1) {
                        size_t ob = (size_t)row * 128 + col;
                        __half2 h = __floats2half2_rn(v0, v1);
                        if (y == 0) *(__half2*)(op + ob) = h;
                        else        *(__half2*)(oq + ob) = h;
                    } else if (MODE == 2) {
                        size_t ob = (size_t)row * 256 + n0 + col;
                        *(__half2*)(op + ob) = __floats2half2_rn(v0, v1);
                    } else {
                        size_t ob = (size_t)row * 256 + n0 + col;
                        float2 vv = __half22float2(*(const __half2*)(vin + ob));
                        v0 = fast_tanh(v0 + vv.x + b0);
                        v1 = fast_tanh(v1 + vv.y + b1);
                        *(__half2*)(oh + ob) = __floats2half2_rn(v0, v1);
                    }
                }
            }
        }
    }
}

// ================= host =================
extern "C" void kernel_launch(void* const* d_in, const int* in_sizes, int n_in,
                              void* d_out, int out_size) {
    (void)in_sizes; (void)n_in; (void)out_size;

    const float* x0  = (const float*)d_in[0];
    const float* x1  = (const float*)d_in[1];
    const int*   ei0 = (const int*)d_in[2];
    const int*   ei1 = (const int*)d_in[3];
    const float* W1l_0 = (const float*)d_in[4];
    const float* b1_0  = (const float*)d_in[5];
    const float* W1r_0 = (const float*)d_in[6];
    const float* W2l_0 = (const float*)d_in[7];
    const float* b2_0  = (const float*)d_in[8];
    const float* W2r_0 = (const float*)d_in[9];
    const float* W1l_1 = (const float*)d_in[10];
    const float* b1_1  = (const float*)d_in[11];
    const float* W1r_1 = (const float*)d_in[12];
    const float* W2l_1 = (const float*)d_in[13];
    const float* b2_1  = (const float*)d_in[14];
    const float* W2r_1 = (const float*)d_in[15];
    float* out = (float*)d_out;

    constexpr int SMEM = 2 * 2 * 10240;  // 40960

    int *count, *row_start, *cursor, *srcsort, *btot, *boff;
    __half *xh16, *af16, *h16, *v, *p, *q16, *wf16;
    cudaGetSymbolAddress((void**)&count, g_count);
    cudaGetSymbolAddress((void**)&row_start, g_row_start);
    cudaGetSymbolAddress((void**)&cursor, g_cursor);
    cudaGetSymbolAddress((void**)&srcsort, g_srcsort);
    cudaGetSymbolAddress((void**)&btot, g_btot);
    cudaGetSymbolAddress((void**)&boff, g_boff);
    cudaGetSymbolAddress((void**)&xh16, g_xh16);
    cudaGetSymbolAddress((void**)&af16, g_af16);
    cudaGetSymbolAddress((void**)&h16, g_h16);
    cudaGetSymbolAddress((void**)&v, g_v);
    cudaGetSymbolAddress((void**)&p, g_p);
    cudaGetSymbolAddress((void**)&q16, g_q16);
    cudaGetSymbolAddress((void**)&wf16, g_wf16);

    SplitJobs J;
    const float* srcs[10] = {x0, x1, W1l_0, W1r_0, W2l_0, W2r_0, W1l_1, W1r_1, W2l_1, W2r_1};
    int counts[10] = {N_NODES * 128, N_NODES * 128,
                      32768, 32768, 32768, 32768, 32768, 32768, 32768, 32768};
    int cum = 0;
    for (int j = 0; j < 10; j++) {
        J.src[j] = srcs[j];
        if (j == 0)      J.f16[j] = xh16;
        else if (j == 1) J.f16[j] = xh16 + (size_t)N_NODES * 128;
        else             J.f16[j] = wf16 + (j - 2) * 32768;
        J.n4cum[j] = cum;
        cum += counts[j] / 4;
    }
    J.n4cum[10] = cum;

    GemmW Wv, Wu, W2;
    for (int g = 0; g < 2; g++) {
        for (int y = 0; y < 2; y++) {
            Wv.b0[y][g] = wf16 + (4 * g + 1) * 32768;
            Wv.b1[y][g] = wf16 + (4 * g + 1) * 32768 + 64;
            Wu.b0[y][g] = wf16 + (4 * g + 0) * 32768;
            Wu.b1[y][g] = wf16 + (4 * g + 0) * 32768 + 64;
        }
        W2.b0[0][g] = wf16 + (4 * g + 2) * 32768;
        W2.b1[0][g] = wf16 + (4 * g + 2) * 32768 + 128;
        W2.b0[1][g] = wf16 + (4 * g + 3) * 32768;
        W2.b1[1][g] = wf16 + (4 * g + 3) * 32768 + 128;
    }
    Wu.bias[0] = b1_0; Wu.bias[1] = b1_1;
    Wv.bias[0] = nullptr; Wv.bias[1] = nullptr;
    W2.bias[0] = nullptr; W2.bias[1] = nullptr;

    cudaStream_t s2;
    cudaStreamCreateWithFlags(&s2, cudaStreamNonBlocking);
    cudaEvent_t evFork, evSplit, evV, evA0, evD0;
    cudaEventCreateWithFlags(&evFork, cudaEventDisableTiming);
    cudaEventCreateWithFlags(&evSplit, cudaEventDisableTiming);
    cudaEventCreateWithFlags(&evV, cudaEventDisableTiming);
    cudaEventCreateWithFlags(&evA0, cudaEventDisableTiming);
    cudaEventCreateWithFlags(&evD0, cudaEventDisableTiming);

    // fork: s2 runs split + v-GEMM, main runs CSR chain concurrently
    cudaEventRecord(evFork, 0);
    cudaStreamWaitEvent(s2, evFork, 0);
    split_all_kernel<<<(cum + 255) / 256, 256, 0, s2>>>(J);
    cudaEventRecord(evSplit, s2);
    {
        dim3 grid(M_TILES, 2, 2);
        sage_mma_kernel<64, 128, 128, 128, 2><<<grid, 256, SMEM, s2>>>(
            xh16, xh16 + 64, Wv, nullptr, v, nullptr, nullptr, 0);
    }
    cudaEventRecord(evV, s2);

    // main: CSR chain (independent of split)
    hist_kernel<<<(ETOT / 2 + 255) / 256, 256>>>(ei0, ei1, count);
    scan_part_kernel<<<SCAN_BLOCKS, 1024>>>(count, row_start, btot);
    scan_tops_kernel<<<1, 128>>>(btot, boff);
    scan_add_kernel<<<SCAN_BLOCKS, 1024>>>(boff, row_start, cursor);
    scatter_kernel<<<(ETOT + 255) / 256, 256>>>(ei0, ei1, cursor, srcsort);

    // main: agg1 needs split output
    cudaStreamWaitEvent(0, evSplit, 0);
    aggregate1_kernel<<<N_NODES / 8, 128>>>(xh16, row_start, srcsort, af16, 0);
    cudaEventRecord(evA0, 0);
    aggregate1_kernel<<<N_NODES / 8, 128>>>(xh16, row_start, srcsort, af16, N_NODES);

    // s2 chain for graph 0
    cudaStreamWaitEvent(s2, evA0, 0);
    {
        dim3 grid(M_TILES, 2, 1);
        sage_mma_kernel<64, 128, 128, 128, 3><<<grid, 256, SMEM, s2>>>(
            af16, af16 + 64, Wu, h16, nullptr, nullptr, v, 0);
        sage_mma_kernel<128, 256, 256, 0, 1><<<grid, 256, SMEM, s2>>>(
            h16, h16 + 128, W2, nullptr, p, q16, nullptr, 0);
    }
    agg_fuse2_kernel<<<N_NODES / 8, 128, 0, s2>>>(p, q16, row_start, srcsort, b2_0, out, 0);
    cudaEventRecord(evD0, s2);

    // main chain for graph 1 (needs v)
    cudaStreamWaitEvent(0, evV, 0);
    {
        dim3 grid(M_TILES, 2, 1);
        sage_mma_kernel<64, 128, 128, 128, 3><<<grid, 256, SMEM>>>(
            af16, af16 + 64, Wu, h16, nullptr, nullptr, v, 1);
        sage_mma_kernel<128, 256, 256, 0, 1><<<grid, 256, SMEM>>>(
            h16, h16 + 128, W2, nullptr, p, q16, nullptr, 1);
    }
    agg_fuse2_kernel<<<N_NODES / 8, 128>>>(p, q16, row_start, srcsort, b2_1, out, N_NODES);

    cudaStreamWaitEvent(0, evD0, 0);

    cudaEventDestroy(evFork);
    cudaEventDestroy(evSplit);
    cudaEventDestroy(evV);
    cudaEventDestroy(evA0);
    cudaEventDestroy(evD0);
    cudaStreamDestroy(s2);
}

// round 13
// speedup vs baseline: 1.8162x; 1.0213x over previous
#include <cuda_runtime.h>
#include <cuda_fp16.h>
#include <math.h>
#include <stdint.h>

#define N_NODES 50000
#define NTOT    (2 * N_NODES)
#define NEDGE   800000
#define ETOT    (2 * NEDGE)
#define M_TILES ((N_NODES + 127) / 128)   // 391 per graph
#define SCAN_BLOCKS_G ((N_NODES + 1023) / 1024)   // 49 per graph

// ================= device scratch =================
__device__ int   g_count[NTOT];
__device__ int   g_row_start[2 * (N_NODES + 1)];
__device__ int   g_cursor[NTOT];
__device__ int   g_srcsort[ETOT];
__device__ int   g_btot[2 * SCAN_BLOCKS_G];
__device__ int   g_boff[2 * SCAN_BLOCKS_G];
__device__ __half g_xh16[(size_t)NTOT * 128];
__device__ __half g_af16[(size_t)NTOT * 128];
__device__ __half g_h16[(size_t)NTOT * 256];
__device__ __half g_v[(size_t)NTOT * 256];
__device__ __half g_p[(size_t)NTOT * 128];
__device__ __half g_q16[(size_t)NTOT * 128];
__device__ __half g_wf16[8 * 32768];

// ================= helpers =================
__device__ __forceinline__ uint32_t smem_u32(const void* p) {
    uint32_t a;
    asm("{ .reg .u64 t; cvta.to.shared.u64 t, %1; cvt.u32.u64 %0, t; }" : "=r"(a) : "l"(p));
    return a;
}
__device__ __forceinline__ void cp_async16(uint32_t dst, const void* src, bool valid) {
    if (valid) {
        asm volatile("cp.async.cg.shared.global [%0], [%1], 16;" :: "r"(dst), "l"(src));
    } else {
        asm volatile("cp.async.cg.shared.global [%0], [%1], 16, %2;"
                     :: "r"(dst), "l"(src), "r"(0u));
    }
}
#define CP_COMMIT()  asm volatile("cp.async.commit_group;" ::: "memory")
#define CP_WAIT1()   asm volatile("cp.async.wait_group 1;" ::: "memory")

__device__ __forceinline__ void ldsm4(uint32_t* r, uint32_t addr) {
    asm volatile("ldmatrix.sync.aligned.m8n8.x4.shared.b16 {%0,%1,%2,%3}, [%4];"
                 : "=r"(r[0]), "=r"(r[1]), "=r"(r[2]), "=r"(r[3]) : "r"(addr));
}
__device__ __forceinline__ void mma16816f16(float* d, const uint32_t* a, const uint32_t* b) {
    asm volatile(
        "mma.sync.aligned.m16n8k16.row.col.f32.f16.f16.f32 "
        "{%0,%1,%2,%3}, {%4,%5,%6,%7}, {%8,%9}, {%0,%1,%2,%3};"
        : "+f"(d[0]), "+f"(d[1]), "+f"(d[2]), "+f"(d[3])
        : "r"(a[0]), "r"(a[1]), "r"(a[2]), "r"(a[3]), "r"(b[0]), "r"(b[1]));
}

__device__ __forceinline__ float fast_tanh(float x) {
    float e = __expf(2.0f * x);
    return 1.0f - __fdividef(2.0f, e + 1.0f);
}

// ================= upfront fp32 -> fp16 conversion =================
struct SplitJobs {
    const float* src[10];
    __half* f16[10];
    int n4cum[11];
};

__global__ void split_all_kernel(SplitJobs J) {
    int f = blockIdx.x * blockDim.x + threadIdx.x;
    if (f >= J.n4cum[10]) return;
    int j = 0;
#pragma unroll
    for (int t = 0; t < 10; t++)
        if (f >= J.n4cum[t + 1]) j = t + 1;
    int local = f - J.n4cum[j];
    float4 v = *(const float4*)(J.src[j] + 4 * (size_t)local);
    __half2 a = __floats2half2_rn(v.x, v.y);
    __half2 b = __floats2half2_rn(v.z, v.w);
    uint2 pk;
    pk.x = *(uint32_t*)&a;
    pk.y = *(uint32_t*)&b;
    *(uint2*)(J.f16[j] + 4 * (size_t)local) = pk;
}

// ================= per-graph CSR build =================
// count: pre-offset per-graph pointer; dst ids are graph-local.
__global__ void hist_g_kernel(const int* __restrict__ ei, int* __restrict__ count) {
    int t = blockIdx.x * blockDim.x + threadIdx.x;
    int e = t * 2;
    if (e >= NEDGE) return;
    int2 d = *(const int2*)(ei + NEDGE + e);
    atomicAdd(&count[d.x], 1);
    atomicAdd(&count[d.y], 1);
}

// per-block exclusive scan over N_NODES graph-local counts; zeroes counts.
__global__ void scan_part_kernel(int* __restrict__ counts, int* __restrict__ row_start,
                                 int* __restrict__ btot) {
    __shared__ int wsum[32];
    int tid = threadIdx.x, lane = tid & 31, w = tid >> 5;
    int i = blockIdx.x * 1024 + tid;
    int v = 0;
    if (i < N_NODES) { v = counts[i]; counts[i] = 0; }
    int x = v;
#pragma unroll
    for (int off = 1; off < 32; off <<= 1) {
        int t = __shfl_up_sync(0xFFFFFFFFu, x, off);
        if (lane >= off) x += t;
    }
    if (lane == 31) wsum[w] = x;
    __syncthreads();
    if (w == 0) {
        int s = wsum[lane];
#pragma unroll
        for (int off = 1; off < 32; off <<= 1) {
            int t = __shfl_up_sync(0xFFFFFFFFu, s, off);
            if (lane >= off) s += t;
        }
        wsum[lane] = s;
    }
    __syncthreads();
    int excl = x - v + (w ? wsum[w - 1] : 0);
    if (i < N_NODES) row_start[i] = excl;
    if (tid == 0) btot[blockIdx.x] = wsum[31];
}

__global__ void scan_tops_kernel(const int* __restrict__ btot, int* __restrict__ boff) {
    __shared__ int sh[64];
    int tid = threadIdx.x;
    int v = (tid < SCAN_BLOCKS_G) ? btot[tid] : 0;
    sh[tid] = v;
    __syncthreads();
    for (int off = 1; off < 64; off <<= 1) {
        int t = (tid >= off) ? sh[tid - off] : 0;
        __syncthreads();
        sh[tid] += t;
        __syncthreads();
    }
    if (tid < SCAN_BLOCKS_G) boff[tid] = sh[tid] - v;
}

// adds block offsets + global edge base; fills row_start[N_NODES] and cursor.
__global__ void scan_add_kernel(const int* __restrict__ boff, int* __restrict__ row_start,
                                int* __restrict__ cursor, int edge_base) {
    int i = blockIdx.x * 1024 + threadIdx.x;
    if (i < N_NODES) {
        int rs = row_start[i] + boff[blockIdx.x] + edge_base;
        row_start[i] = rs;
        cursor[i] = rs;
    }
    if (i == N_NODES - 1) row_start[N_NODES] = edge_base + NEDGE;
}

// cursor: per-graph pointer (graph-local dst); srcsort global ids.
__global__ void scatter_g_kernel(const int* __restrict__ ei, int node_base,
                                 int* __restrict__ cursor, int* __restrict__ srcsort) {
    int e = blockIdx.x * blockDim.x + threadIdx.x;
    if (e >= NEDGE) return;
    int s = ei[e] + node_base;
    int d = ei[NEDGE + e];
    int p = atomicAdd(&cursor[d], 1);
    srcsort[p] = s;
}

// ================= layer-1 mean aggregation (16B loads, 8 nodes/block) ============
// rs: per-graph row_start pointer (graph-local index)
__global__ void aggregate1_kernel(const __half* __restrict__ xh,
                                  const int* __restrict__ rs,
                                  const int* __restrict__ srcsort,
                                  __half* __restrict__ oa, int node_base) {
    int local = threadIdx.x >> 4;
    int t8 = (threadIdx.x & 15) * 8;
    int ln = blockIdx.x * 8 + local;
    int node = node_base + ln;
    int s0 = rs[ln];
    int s1 = rs[ln + 1];
    float a[8];
#pragma unroll
    for (int i = 0; i < 8; i++) a[i] = 0.f;
    int e = s0;
    for (; e + 2 <= s1; e += 2) {
        uint4 vA = *(const uint4*)(xh + (size_t)srcsort[e] * 128 + t8);
        uint4 vB = *(const uint4*)(xh + (size_t)srcsort[e + 1] * 128 + t8);
        const uint32_t* wA = &vA.x;
        const uint32_t* wB = &vB.x;
#pragma unroll
        for (int i = 0; i < 4; i++) {
            float2 fA = __half22float2(*(__half2*)&wA[i]);
            float2 fB = __half22float2(*(__half2*)&wB[i]);
            a[2 * i] += fA.x + fB.x;
            a[2 * i + 1] += fA.y + fB.y;
        }
    }
    if (e < s1) {
        uint4 v = *(const uint4*)(xh + (size_t)srcsort[e] * 128 + t8);
        const uint32_t* w = &v.x;
#pragma unroll
        for (int i = 0; i < 4; i++) {
            float2 f = __half22float2(*(__half2*)&w[i]);
            a[2 * i] += f.x;
            a[2 * i + 1] += f.y;
        }
    }
    float inv = 1.0f / (float)max(s1 - s0, 1);
    uint4 pk;
    uint32_t* pw = &pk.x;
#pragma unroll
    for (int i = 0; i < 4; i++) {
        __half2 h = __floats2half2_rn(a[2 * i] * inv, a[2 * i + 1] * inv);
        pw[i] = *(uint32_t*)&h;
    }
    *(uint4*)(oa + (size_t)node * 128 + t8) = pk;
}

// ================= layer-2 fused aggregation + epilogue =================
__global__ void agg_fuse2_kernel(const __half* __restrict__ p,
                                 const __half* __restrict__ q,
                                 const int* __restrict__ rs,
                                 const int* __restrict__ srcsort,
                                 const float* __restrict__ bias,
                                 float* __restrict__ out, int node_base) {
    int local = threadIdx.x >> 4;
    int t8 = (threadIdx.x & 15) * 8;
    int ln = blockIdx.x * 8 + local;
    int node = node_base + ln;
    int s0 = rs[ln];
    int s1 = rs[ln + 1];
    float a[8];
#pragma unroll
    for (int i = 0; i < 8; i++) a[i] = 0.f;
    int e = s0;
    for (; e + 2 <= s1; e += 2) {
        uint4 vA = *(const uint4*)(p + (size_t)srcsort[e] * 128 + t8);
        uint4 vB = *(const uint4*)(p + (size_t)srcsort[e + 1] * 128 + t8);
        const uint32_t* wA = &vA.x;
        const uint32_t* wB = &vB.x;
#pragma unroll
        for (int i = 0; i < 4; i++) {
            float2 fA = __half22float2(*(__half2*)&wA[i]);
            float2 fB = __half22float2(*(__half2*)&wB[i]);
            a[2 * i] += fA.x + fB.x;
            a[2 * i + 1] += fA.y + fB.y;
        }
    }
    if (e < s1) {
        uint4 v = *(const uint4*)(p + (size_t)srcsort[e] * 128 + t8);
        const uint32_t* w = &v.x;
#pragma unroll
        for (int i = 0; i < 4; i++) {
            float2 f = __half22float2(*(__half2*)&w[i]);
            a[2 * i] += f.x;
            a[2 * i + 1] += f.y;
        }
    }
    float inv = 1.0f / (float)max(s1 - s0, 1);
    uint4 qv = *(const uint4*)(q + (size_t)node * 128 + t8);
    const uint32_t* qw = &qv.x;
    float4 b0 = *(const float4*)(bias + t8);
    float4 b1 = *(const float4*)(bias + t8 + 4);
    float qq[8];
#pragma unroll
    for (int i = 0; i < 4; i++) {
        float2 f = __half22float2(*(__half2*)&qw[i]);
        qq[2 * i] = f.x;
        qq[2 * i + 1] = f.y;
    }
    float4 o0, o1;
    o0.x = fast_tanh(a[0] * inv + qq[0] + b0.x);
    o0.y = fast_tanh(a[1] * inv + qq[1] + b0.y);
    o0.z = fast_tanh(a[2] * inv + qq[2] + b0.z);
    o0.w = fast_tanh(a[3] * inv + qq[3] + b0.w);
    o1.x = fast_tanh(a[4] * inv + qq[4] + b1.x);
    o1.y = fast_tanh(a[5] * inv + qq[5] + b1.y);
    o1.z = fast_tanh(a[6] * inv + qq[6] + b1.z);
    o1.w = fast_tanh(a[7] * inv + qq[7] + b1.w);
    *(float4*)(out + (size_t)node * 128 + t8) = o0;
    *(float4*)(out + (size_t)node * 128 + t8 + 4) = o1;
}

// ================= fp16 mma.sync GEMM =================
struct GemmW {
    const __half* b0[2][2];
    const __half* b1[2][2];
    const float* bias[2];
};

// MODE 1: layer2 p/q (both fp16) ; MODE 2: v = x@W1r^T ; MODE 3: h = tanh(acc+v+bias)
template <int KHALF, int ASTRIDE, int BSTRIDE, int BOFF, int MODE>
__global__ void __launch_bounds__(256, 2)
sage_mma_kernel(const __half* __restrict__ a0, const __half* __restrict__ a1,
                GemmW W,
                __half* __restrict__ oh, __half* __restrict__ op,
                __half* __restrict__ oq, const __half* __restrict__ vin, int gbase) {
    constexpr int NC = 2 * KHALF / 32;
    constexpr int MATB = 10240;
    constexpr int STAGE = 2 * MATB;
    constexpr int MT = 4;

    extern __shared__ char smem[];
    uint32_t sb = smem_u32(smem);

    int tid = threadIdx.x;
    int wid = tid >> 5;
    int lane = tid & 31;
    int wm = wid & 1;
    int wn = wid >> 1;
    int y = blockIdx.y;
    int g = gbase + blockIdx.z;
    int m0 = g * N_NODES + blockIdx.x * 128;
    int Mlim = (g + 1) * N_NODES;
    int n0 = y * 128;
    int bn0 = y * BOFF;

    const __half* B0 = W.b0[y][g];
    const __half* B1 = W.b1[y][g];

    auto issue = [&](int c) {
        int half = (c * 32 >= KHALF) ? 1 : 0;
        int kh0 = c * 32 - half * KHALF;
        const __half* A = half ? a1 : a0;
        const __half* B = half ? B1 : B0;
        uint32_t st = sb + (c & 1) * STAGE;
#pragma unroll
        for (int i = 0; i < 4; i++) {
            int idx = i * 256 + tid;
            int r = idx >> 2;
            int ch = idx & 3;
            if (r < 128) {
                int m = m0 + r;
                bool valid = (m < Mlim);
                const __half* pp = A + (size_t)(valid ? m : 0) * ASTRIDE + kh0 + ch * 8;
                cp_async16(st + r * 80 + ch * 16, pp, valid);
            } else {
                int rl = r - 128;
                cp_async16(st + MATB + rl * 80 + ch * 16,
                           B + (size_t)(bn0 + rl) * BSTRIDE + kh0 + ch * 8, true);
            }
        }
    };

    float acc[MT][4][4];
#pragma unroll
    for (int i = 0; i < MT; i++)
#pragma unroll
        for (int j = 0; j < 4; j++)
#pragma unroll
            for (int k = 0; k < 4; k++) acc[i][j][k] = 0.f;

    issue(0); CP_COMMIT();
    issue(1); CP_COMMIT();

    uint32_t a_row = (uint32_t)(wm * 64 + (lane & 15)) * 80 + (lane >> 4) * 16;
    uint32_t b_row = (uint32_t)(wn * 32 + (lane & 7) + ((lane >> 4) << 3)) * 80 +
                     ((lane >> 3) & 1) * 16;

    for (int c = 0; c < NC; c++) {
        CP_WAIT1();
        __syncthreads();
        uint32_t st = sb + (c & 1) * STAGE;
#pragma unroll
        for (int ks = 0; ks < 2; ks++) {
            uint32_t ko = ks * 32;
            uint32_t Af[MT][4], Bf[2][4];
#pragma unroll
            for (int mt = 0; mt < MT; mt++)
                ldsm4(Af[mt], st + a_row + (uint32_t)mt * (16 * 80) + ko);
#pragma unroll
            for (int nt2 = 0; nt2 < 2; nt2++)
                ldsm4(Bf[nt2], st + MATB + b_row + (uint32_t)nt2 * (16 * 80) + ko);
#pragma unroll
            for (int mt = 0; mt < MT; mt++) {
#pragma unroll
                for (int nt = 0; nt < 4; nt++) {
                    mma16816f16(acc[mt][nt], Af[mt], &Bf[nt >> 1][(nt & 1) * 2]);
                }
            }
        }
        __syncthreads();
        if (c + 2 < NC) issue(c + 2);
        CP_COMMIT();
    }

    int gq = lane >> 2, t4 = lane & 3;
    const float* bias = (MODE == 3) ? W.bias[g] : nullptr;
#pragma unroll
    for (int mt = 0; mt < MT; mt++) {
#pragma unroll
        for (int nt = 0; nt < 4; nt++) {
            int col = wn * 32 + nt * 8 + 2 * t4;
            float b0 = (MODE == 3) ? bias[n0 + col] : 0.f;
            float b1 = (MODE == 3) ? bias[n0 + col + 1] : 0.f;
#pragma unroll
            for (int hrow = 0; hrow < 2; hrow++) {
                int row = m0 + wm * 64 + mt * 16 + gq + hrow * 8;
                if (row < Mlim) {
                    float v0 = acc[mt][nt][2 * hrow + 0];
                    float v1 = acc[mt][nt][2 * hrow + 1];
                    if (MODE == 1) {
                        size_t ob = (size_t)row * 128 + col;
                        __half2 h = __floats2half2_rn(v0, v1);
                        if (y == 0) *(__half2*)(op + ob) = h;
                        else        *(__half2*)(oq + ob) = h;
                    } else if (MODE == 2) {
                        size_t ob = (size_t)row * 256 + n0 + col;
                        *(__half2*)(op + ob) = __floats2half2_rn(v0, v1);
                    } else {
                        size_t ob = (size_t)row * 256 + n0 + col;
                        float2 vv = __half22float2(*(const __half2*)(vin + ob));
                        v0 = fast_tanh(v0 + vv.x + b0);
                        v1 = fast_tanh(v1 + vv.y + b1);
                        *(__half2*)(oh + ob) = __floats2half2_rn(v0, v1);
                    }
                }
            }
        }
    }
}

// ================= host =================
extern "C" void kernel_launch(void* const* d_in, const int* in_sizes, int n_in,
                              void* d_out, int out_size) {
    (void)in_sizes; (void)n_in; (void)out_size;

    const float* x0  = (const float*)d_in[0];
    const float* x1  = (const float*)d_in[1];
    const int*   ei0 = (const int*)d_in[2];
    const int*   ei1 = (const int*)d_in[3];
    const float* W1l_0 = (const float*)d_in[4];
    const float* b1_0  = (const float*)d_in[5];
    const float* W1r_0 = (const float*)d_in[6];
    const float* W2l_0 = (const float*)d_in[7];
    const float* b2_0  = (const float*)d_in[8];
    const float* W2r_0 = (const float*)d_in[9];
    const float* W1l_1 = (const float*)d_in[10];
    const float* b1_1  = (const float*)d_in[11];
    const float* W1r_1 = (const float*)d_in[12];
    const float* W2l_1 = (const float*)d_in[13];
    const float* b2_1  = (const float*)d_in[14];
    const float* W2r_1 = (const float*)d_in[15];
    float* out = (float*)d_out;

    constexpr int SMEM = 2 * 2 * 10240;  // 40960

    int *count, *row_start, *cursor, *srcsort, *btot, *boff;
    __half *xh16, *af16, *h16, *v, *p, *q16, *wf16;
    cudaGetSymbolAddress((void**)&count, g_count);
    cudaGetSymbolAddress((void**)&row_start, g_row_start);
    cudaGetSymbolAddress((void**)&cursor, g_cursor);
    cudaGetSymbolAddress((void**)&srcsort, g_srcsort);
    cudaGetSymbolAddress((void**)&btot, g_btot);
    cudaGetSymbolAddress((void**)&boff, g_boff);
    cudaGetSymbolAddress((void**)&xh16, g_xh16);
    cudaGetSymbolAddress((void**)&af16, g_af16);
    cudaGetSymbolAddress((void**)&h16, g_h16);
    cudaGetSymbolAddress((void**)&v, g_v);
    cudaGetSymbolAddress((void**)&p, g_p);
    cudaGetSymbolAddress((void**)&q16, g_q16);
    cudaGetSymbolAddress((void**)&wf16, g_wf16);

    SplitJobs J;
    const float* srcs[10] = {x0, x1, W1l_0, W1r_0, W2l_0, W2r_0, W1l_1, W1r_1, W2l_1, W2r_1};
    int counts[10] = {N_NODES * 128, N_NODES * 128,
                      32768, 32768, 32768, 32768, 32768, 32768, 32768, 32768};
    int cum = 0;
    for (int j = 0; j < 10; j++) {
        J.src[j] = srcs[j];
        if (j == 0)      J.f16[j] = xh16;
        else if (j == 1) J.f16[j] = xh16 + (size_t)N_NODES * 128;
        else             J.f16[j] = wf16 + (j - 2) * 32768;
        J.n4cum[j] = cum;
        cum += counts[j] / 4;
    }
    J.n4cum[10] = cum;

    GemmW Wv, Wu, W2;
    for (int g = 0; g < 2; g++) {
        for (int y = 0; y < 2; y++) {
            Wv.b0[y][g] = wf16 + (4 * g + 1) * 32768;
            Wv.b1[y][g] = wf16 + (4 * g + 1) * 32768 + 64;
            Wu.b0[y][g] = wf16 + (4 * g + 0) * 32768;
            Wu.b1[y][g] = wf16 + (4 * g + 0) * 32768 + 64;
        }
        W2.b0[0][g] = wf16 + (4 * g + 2) * 32768;
        W2.b1[0][g] = wf16 + (4 * g + 2) * 32768 + 128;
        W2.b0[1][g] = wf16 + (4 * g + 3) * 32768;
        W2.b1[1][g] = wf16 + (4 * g + 3) * 32768 + 128;
    }
    Wu.bias[0] = b1_0; Wu.bias[1] = b1_1;
    Wv.bias[0] = nullptr; Wv.bias[1] = nullptr;
    W2.bias[0] = nullptr; W2.bias[1] = nullptr;

    // per-graph pointers
    int* rs0 = row_start;
    int* rs1 = row_start + (N_NODES + 1);
    int* cur0 = cursor;
    int* cur1 = cursor + N_NODES;
    int* cnt0 = count;
    int* cnt1 = count + N_NODES;

    cudaStream_t s2, s3;
    cudaStreamCreateWithFlags(&s2, cudaStreamNonBlocking);
    cudaStreamCreateWithFlags(&s3, cudaStreamNonBlocking);
    cudaEvent_t evFork, evSplit, evV, evD1;
    cudaEventCreateWithFlags(&evFork, cudaEventDisableTiming);
    cudaEventCreateWithFlags(&evSplit, cudaEventDisableTiming);
    cudaEventCreateWithFlags(&evV, cudaEventDisableTiming);
    cudaEventCreateWithFlags(&evD1, cudaEventDisableTiming);

    cudaEventRecord(evFork, 0);
    cudaStreamWaitEvent(s2, evFork, 0);
    cudaStreamWaitEvent(s3, evFork, 0);

    // s2: split + v-GEMM (both graphs)
    split_all_kernel<<<(cum + 255) / 256, 256, 0, s2>>>(J);
    cudaEventRecord(evSplit, s2);
    {
        dim3 grid(M_TILES, 2, 2);
        sage_mma_kernel<64, 128, 128, 128, 2><<<grid, 256, SMEM, s2>>>(
            xh16, xh16 + 64, Wv, nullptr, v, nullptr, nullptr, 0);
    }
    cudaEventRecord(evV, s2);

    // ===== graph-0 chain on main =====
    hist_g_kernel<<<(NEDGE / 2 + 255) / 256, 256>>>(ei0, cnt0);
    scan_part_kernel<<<SCAN_BLOCKS_G, 1024>>>(cnt0, rs0, btot);
    scan_tops_kernel<<<1, 64>>>(btot, boff);
    scan_add_kernel<<<SCAN_BLOCKS_G, 1024>>>(boff, rs0, cur0, 0);
    scatter_g_kernel<<<(NEDGE + 255) / 256, 256>>>(ei0, 0, cur0, srcsort);
    cudaStreamWaitEvent(0, evSplit, 0);
    aggregate1_kernel<<<N_NODES / 8, 128>>>(xh16, rs0, srcsort, af16, 0);
    cudaStreamWaitEvent(0, evV, 0);
    {
        dim3 grid(M_TILES, 2, 1);
        sage_mma_kernel<64, 128, 128, 128, 3><<<grid, 256, SMEM>>>(
            af16, af16 + 64, Wu, h16, nullptr, nullptr, v, 0);
        sage_mma_kernel<128, 256, 256, 0, 1><<<grid, 256, SMEM>>>(
            h16, h16 + 128, W2, nullptr, p, q16, nullptr, 0);
    }
    agg_fuse2_kernel<<<N_NODES / 8, 128>>>(p, q16, rs0, srcsort, b2_0, out, 0);

    // ===== graph-1 chain on s3 =====
    hist_g_kernel<<<(NEDGE / 2 + 255) / 256, 256, 0, s3>>>(ei1, cnt1);
    scan_part_kernel<<<SCAN_BLOCKS_G, 1024, 0, s3>>>(cnt1, rs1, btot + SCAN_BLOCKS_G);
    scan_tops_kernel<<<1, 64, 0, s3>>>(btot + SCAN_BLOCKS_G, boff + SCAN_BLOCKS_G);
    scan_add_kernel<<<SCAN_BLOCKS_G, 1024, 0, s3>>>(boff + SCAN_BLOCKS_G, rs1, cur1, NEDGE);
    scatter_g_kernel<<<(NEDGE + 255) / 256, 256, 0, s3>>>(ei1, N_NODES, cur1, srcsort);
    cudaStreamWaitEvent(s3, evSplit, 0);
    aggregate1_kernel<<<N_NODES / 8, 128, 0, s3>>>(xh16, rs1, srcsort, af16, N_NODES);
    cudaStreamWaitEvent(s3, evV, 0);
    {
        dim3 grid(M_TILES, 2, 1);
        sage_mma_kernel<64, 128, 128, 128, 3><<<grid, 256, SMEM, s3>>>(
            af16, af16 + 64, Wu, h16, nullptr, nullptr, v, 1);
        sage_mma_kernel<128, 256, 256, 0, 1><<<grid, 256, SMEM, s3>>>(
            h16, h16 + 128, W2, nullptr, p, q16, nullptr, 1);
    }
    agg_fuse2_kernel<<<N_NODES / 8, 128, 0, s3>>>(p, q16, rs1, srcsort, b2_1, out, N_NODES);
    cudaEventRecord(evD1, s3);

    // join
    cudaStreamWaitEvent(0, evD1, 0);

    cudaEventDestroy(evFork);
    cudaEventDestroy(evSplit);
    cudaEventDestroy(evV);
    cudaEventDestroy(evD1);
    cudaStreamDestroy(s2);
    cudaStreamDestroy(s3);
}